// round 1
// baseline (speedup 1.0000x reference)
#include <cuda_runtime.h>
#include <math.h>

// ---------------- problem constants ----------------
#define Bz   64
#define PANO 36
#define OBJ  36
#define CFG  16
#define LM   8
#define IMG  32
#define Dd   300
#define Hh   512
#define EMB  64
#define ANG  128
#define FEAT 2176
#define TOPN 3
#define Mm   128          // CFG*LM
#define FEAT_ALL 3076     // FEAT + TOPN*D
#define XDIM 3140         // EMB + FEAT_ALL
#define G4   2048         // 4*H
#define CAND_ALL 3097     // FEAT + TOPN*7 + TOPN*D
#define EPSV 1e-8f

// ---------------- scratch (static device globals; no allocation) ----------------
__device__ int   g_top_idx[Bz * TOPN];
__device__ int   g_ctop[Bz * TOPN];
__device__ float g_land_sel[Bz * TOPN * Dd];
__device__ float g_land_norm[Bz * TOPN];
__device__ float g_cland[Bz * TOPN * Dd];
__device__ float g_cland_norm[Bz * TOPN];
__device__ float g_lrel[Bz * TOPN * 6];
__device__ float g_rmask[Bz * TOPN];
__device__ float g_pano_sim[(size_t)Bz * PANO * TOPN * Dd];  // 8.3 MB
__device__ float g_q_feat[Bz * FEAT_ALL];
__device__ float g_attn_p[Bz * PANO];
__device__ float g_x[Bz * XDIM];
__device__ float g_gates[Bz * G4];
__device__ float g_q2[Bz * Hh];
__device__ float g_cat[Bz * 2 * Hh];
__device__ float g_q_cand[Bz * CAND_ALL];

// ---------------- helpers ----------------
__device__ __forceinline__ float warp_sum(float v) {
    #pragma unroll
    for (int off = 16; off > 0; off >>= 1) v += __shfl_xor_sync(0xffffffffu, v, off);
    return v;
}
__device__ __forceinline__ float sigmoidf(float x) { return 1.0f / (1.0f + expf(-x)); }

// ---------------- K_select: top-3 of (weights x landmark_mask), gather land rows + norms ----------------
// mode 0: pano side (s_0 weights). mode 1: candidate side (ctx_attn weights) + relation gathers.
__global__ void k_select(const float* __restrict__ weights,   // [B,CFG]
                         const float* __restrict__ lmask,     // [B,M]
                         const float* __restrict__ land,      // [B,M,D]
                         int* __restrict__ out_idx,           // [B,3]
                         float* __restrict__ out_rows,        // [B,3,D]
                         float* __restrict__ out_norm,        // [B,3]
                         const float* __restrict__ lrel_src,  // [B,M,6] or null
                         const float* __restrict__ rmask_src, // [B,M] or null
                         float* __restrict__ out_lrel,        // [B,3,6]
                         float* __restrict__ out_rmask,       // [B,3]
                         int mode)
{
    int b = blockIdx.x;
    int t = threadIdx.x;  // 128 threads
    __shared__ float v[Mm];
    __shared__ int bidx[TOPN];
    __shared__ float red[128];

    v[t] = weights[b * CFG + (t >> 3)] * lmask[b * Mm + t];
    __syncthreads();
    if (t == 0) {
        for (int rep = 0; rep < TOPN; rep++) {
            float bv = v[0]; int bi = 0;
            for (int m = 1; m < Mm; m++) { float x = v[m]; if (x > bv) { bv = x; bi = m; } }
            bidx[rep] = bi; v[bi] = -3.4e38f;
        }
    }
    __syncthreads();
    if (t < TOPN) out_idx[b * TOPN + t] = bidx[t];

    for (int tt = 0; tt < TOPN; tt++) {
        int m = bidx[tt];
        const float* src = land + ((size_t)(b * Mm + m)) * Dd;
        float part = 0.f;
        for (int j = t; j < Dd; j += 128) {
            float x = src[j];
            out_rows[((size_t)(b * TOPN + tt)) * Dd + j] = x;
            part += x * x;
        }
        red[t] = part; __syncthreads();
        for (int off = 64; off > 0; off >>= 1) { if (t < off) red[t] += red[t + off]; __syncthreads(); }
        if (t == 0) out_norm[b * TOPN + tt] = sqrtf(red[0]);
        __syncthreads();
    }

    if (mode == 1) {
        if (t < TOPN * 6) {
            int tt = t / 6, r = t % 6;
            out_lrel[(b * TOPN + tt) * 6 + r] = lrel_src[((size_t)(b * Mm + bidx[tt])) * 6 + r];
        }
        if (t < TOPN) out_rmask[b * TOPN + t] = rmask_src[b * Mm + bidx[t]];
    }
}

// ---------------- K_pano: cosine argmax over 36 objects vs 3 selected land rows; gather rows ----------------
__global__ void k_pano(const float* __restrict__ pano_obj,  // [B,PANO,OBJ,D]
                       const float* __restrict__ land_sel,  // [B,3,D]
                       const float* __restrict__ land_norm, // [B,3]
                       float* __restrict__ pano_sim)        // [B,PANO,3,D]
{
    int b = blockIdx.y, p = blockIdx.x;
    int tid = threadIdx.x;              // 256
    int warp = tid >> 5, lane = tid & 31;
    __shared__ float land[TOPN][Dd];
    __shared__ float lnorm[TOPN];
    __shared__ float sim[OBJ][TOPN];
    __shared__ int best[TOPN];

    for (int idx = tid; idx < TOPN * Dd; idx += 256)
        land[idx / Dd][idx % Dd] = land_sel[(size_t)b * TOPN * Dd + idx];
    if (tid < TOPN) lnorm[tid] = land_norm[b * TOPN + tid];
    __syncthreads();

    const float* obase = pano_obj + ((size_t)(b * PANO + p)) * OBJ * Dd;
    for (int o = warp; o < OBJ; o += 8) {
        const float* row = obase + (size_t)o * Dd;
        float a0 = 0, a1 = 0, a2 = 0, an = 0;
        for (int j = lane; j < Dd; j += 32) {
            float x = row[j];
            a0 += x * land[0][j]; a1 += x * land[1][j]; a2 += x * land[2][j]; an += x * x;
        }
        a0 = warp_sum(a0); a1 = warp_sum(a1); a2 = warp_sum(a2); an = warp_sum(an);
        if (lane == 0) {
            float no = sqrtf(an);
            sim[o][0] = a0 / fmaxf(no * lnorm[0], EPSV);
            sim[o][1] = a1 / fmaxf(no * lnorm[1], EPSV);
            sim[o][2] = a2 / fmaxf(no * lnorm[2], EPSV);
        }
    }
    __syncthreads();
    if (tid < TOPN) {
        float bv = sim[0][tid]; int bi = 0;
        for (int o = 1; o < OBJ; o++) { float s = sim[o][tid]; if (s > bv) { bv = s; bi = o; } }
        best[tid] = bi;
    }
    __syncthreads();
    for (int tt = 0; tt < TOPN; tt++) {
        const float* row = obase + (size_t)best[tt] * Dd;
        float* dst = pano_sim + (((size_t)(b * PANO + p)) * TOPN + tt) * Dd;
        for (int j = tid; j < Dd; j += 256) dst[j] = row[j];
    }
}

// ---------------- K_actemb: tanh(action @ emb_W + emb_b) -> g_x[:, :64] ----------------
__global__ void k_actemb(const float* __restrict__ action, const float* __restrict__ embW,
                         const float* __restrict__ embb, float* __restrict__ x)
{
    int b = blockIdx.x, e = threadIdx.x;  // 64 threads
    float acc = 0.f;
    #pragma unroll 4
    for (int a = 0; a < ANG; a++) acc += action[b * ANG + a] * embW[a * EMB + e];
    x[(size_t)b * XDIM + e] = tanhf(acc + embb[e]);
}

// ---------------- generic skinny GEMM: out[b,j] = act( A[b,:]@W[:,j] + bias[j] ) (optional accumulate) ----
__global__ void sgemm_tn(const float* __restrict__ A, const float* __restrict__ W,
                         const float* __restrict__ bias, float* __restrict__ out,
                         int K, int N, int act, int accum)
{
    int j = blockIdx.x * 32 + threadIdx.x;
    int b = blockIdx.y * 8 + threadIdx.y;
    if (j >= N) return;
    const float* a = A + (size_t)b * K;
    float acc0 = 0, acc1 = 0, acc2 = 0, acc3 = 0;
    int k = 0;
    for (; k + 4 <= K; k += 4) {
        acc0 += a[k]     * W[(size_t)k       * N + j];
        acc1 += a[k + 1] * W[(size_t)(k + 1) * N + j];
        acc2 += a[k + 2] * W[(size_t)(k + 2) * N + j];
        acc3 += a[k + 3] * W[(size_t)(k + 3) * N + j];
    }
    for (; k < K; k++) acc0 += a[k] * W[(size_t)k * N + j];
    float r = (acc0 + acc1) + (acc2 + acc3);
    if (bias) r += bias[j];
    if (act) r = tanhf(r);
    if (accum) out[(size_t)b * N + j] += r;
    else       out[(size_t)b * N + j] = r;
}

// ---------------- K_attn_a: attention logits + softmax over 36 pano views ----------------
__global__ void k_attn_a(const float* __restrict__ feature,   // [B,36,FEAT]
                         const float* __restrict__ pano_sim,  // [B,36,900]
                         const float* __restrict__ q,         // [B,3076]
                         float* __restrict__ attn_p)          // [B,36]
{
    int b = blockIdx.x;
    int tid = threadIdx.x, warp = tid >> 5, lane = tid & 31; // 256 threads
    __shared__ float aval[PANO];
    __shared__ float pvals[PANO];
    const float* qb = q + (size_t)b * FEAT_ALL;
    for (int s = warp; s < PANO; s += 8) {
        const float* f  = feature  + ((size_t)(b * PANO + s)) * FEAT;
        const float* ps = pano_sim + ((size_t)(b * PANO + s)) * TOPN * Dd;
        float acc = 0.f;
        for (int j = lane; j < FEAT; j += 32) acc += f[j] * qb[j];
        for (int j = lane; j < TOPN * Dd; j += 32) acc += ps[j] * qb[FEAT + j];
        acc = warp_sum(acc);
        if (lane == 0) aval[s] = acc;
    }
    __syncthreads();
    if (tid == 0) {
        float mx = aval[0];
        for (int s = 1; s < PANO; s++) mx = fmaxf(mx, aval[s]);
        float sum = 0.f;
        for (int s = 0; s < PANO; s++) { float e = expf(aval[s] - mx); pvals[s] = e; sum += e; }
        float inv = 1.0f / sum;
        for (int s = 0; s < PANO; s++) pvals[s] *= inv;
    }
    __syncthreads();
    if (tid < PANO) attn_p[b * PANO + tid] = pvals[tid];
}

// ---------------- K_attn_feat: attn_feat[b,j] = sum_s p[s]*feat_all[b,s,j] -> g_x[:, 64:] ----------------
__global__ void k_attn_feat(const float* __restrict__ feature, const float* __restrict__ pano_sim,
                            const float* __restrict__ attn_p, float* __restrict__ x)
{
    int b = blockIdx.y;
    int j = blockIdx.x * 128 + threadIdx.x;
    if (j >= FEAT_ALL) return;
    float acc = 0.f;
    if (j < FEAT) {
        #pragma unroll 4
        for (int s = 0; s < PANO; s++)
            acc += attn_p[b * PANO + s] * feature[((size_t)(b * PANO + s)) * FEAT + j];
    } else {
        int jj = j - FEAT;
        #pragma unroll 4
        for (int s = 0; s < PANO; s++)
            acc += attn_p[b * PANO + s] * pano_sim[((size_t)(b * PANO + s)) * TOPN * Dd + jj];
    }
    x[(size_t)b * XDIM + EMB + j] = acc;
}

// ---------------- K_cell: LSTM elementwise ----------------
__global__ void k_cell(const float* __restrict__ gates, const float* __restrict__ c0,
                       float* __restrict__ h1, float* __restrict__ c1)
{
    int idx = blockIdx.x * 256 + threadIdx.x;
    if (idx >= Bz * Hh) return;
    int b = idx / Hh, h = idx % Hh;
    const float* g = gates + (size_t)b * G4;
    float ig = sigmoidf(g[h]);
    float fg = sigmoidf(g[Hh + h]);
    float gg = tanhf(g[2 * Hh + h]);
    float og = sigmoidf(g[3 * Hh + h]);
    float c = fg * c0[idx] + ig * gg;
    c1[idx] = c;
    h1[idx] = og * tanhf(c);
}

// ---------------- K_ctx: ctx attention (softmax over 16), wctx, build [wctx,h1] ----------------
__global__ void k_ctx(const float* __restrict__ ctx,  // [B,16,512]
                      const float* __restrict__ q2,   // [B,512]
                      const float* __restrict__ h1,   // [B,512]
                      float* __restrict__ ctx_attn,   // [B,16] (output)
                      float* __restrict__ cat)        // [B,1024]
{
    int b = blockIdx.x;
    int tid = threadIdx.x, warp = tid >> 5, lane = tid & 31; // 512 threads = 16 warps
    __shared__ float lg[CFG];
    __shared__ float pr[CFG];
    {
        int s = warp;
        const float* c = ctx + ((size_t)(b * CFG + s)) * Hh;
        const float* q = q2 + (size_t)b * Hh;
        float acc = 0.f;
        for (int j = lane; j < Hh; j += 32) acc += c[j] * q[j];
        acc = warp_sum(acc);
        if (lane == 0) lg[s] = acc;
    }
    __syncthreads();
    if (tid == 0) {
        float mx = lg[0];
        for (int s = 1; s < CFG; s++) mx = fmaxf(mx, lg[s]);
        float sum = 0.f;
        for (int s = 0; s < CFG; s++) { float e = expf(lg[s] - mx); pr[s] = e; sum += e; }
        float inv = 1.0f / sum;
        for (int s = 0; s < CFG; s++) pr[s] *= inv;
    }
    __syncthreads();
    if (tid < CFG) ctx_attn[b * CFG + tid] = pr[tid];
    // wctx + concat with h1
    float acc = 0.f;
    #pragma unroll
    for (int s = 0; s < CFG; s++) acc += pr[s] * ctx[((size_t)(b * CFG + s)) * Hh + tid];
    cat[(size_t)b * 2 * Hh + tid] = acc;
    cat[(size_t)b * 2 * Hh + Hh + tid] = h1[(size_t)b * Hh + tid];
}

// ---------------- K_logit: candidate cosine argmax (3 rows) + final logit dot ----------------
__global__ void k_logit(const float* __restrict__ cand_obj,   // [B,IMG,OBJ,D]
                        const float* __restrict__ cland,      // [B,3,D]
                        const float* __restrict__ cland_norm, // [B,3]
                        const float* __restrict__ cand_feat,  // [B,IMG,FEAT]
                        const float* __restrict__ crel_in,    // [B,IMG,6]
                        const float* __restrict__ lrel,       // [B,3,6]
                        const float* __restrict__ rmask,      // [B,3]
                        const float* __restrict__ q3,         // [B,3097]
                        float* __restrict__ logit)            // [B,IMG]
{
    int b = blockIdx.y, i = blockIdx.x;
    int tid = threadIdx.x, warp = tid >> 5, lane = tid & 31; // 256 threads
    __shared__ float land[TOPN][Dd];
    __shared__ float lnorm[TOPN];
    __shared__ float sim[OBJ][TOPN];
    __shared__ int best[TOPN];
    __shared__ float red[256];

    for (int idx = tid; idx < TOPN * Dd; idx += 256)
        land[idx / Dd][idx % Dd] = cland[(size_t)b * TOPN * Dd + idx];
    if (tid < TOPN) lnorm[tid] = cland_norm[b * TOPN + tid];
    __syncthreads();

    const float* obase = cand_obj + ((size_t)(b * IMG + i)) * OBJ * Dd;
    for (int o = warp; o < OBJ; o += 8) {
        const float* row = obase + (size_t)o * Dd;
        float a0 = 0, a1 = 0, a2 = 0, an = 0;
        for (int j = lane; j < Dd; j += 32) {
            float x = row[j];
            a0 += x * land[0][j]; a1 += x * land[1][j]; a2 += x * land[2][j]; an += x * x;
        }
        a0 = warp_sum(a0); a1 = warp_sum(a1); a2 = warp_sum(a2); an = warp_sum(an);
        if (lane == 0) {
            float no = sqrtf(an);
            sim[o][0] = a0 / fmaxf(no * lnorm[0], EPSV);
            sim[o][1] = a1 / fmaxf(no * lnorm[1], EPSV);
            sim[o][2] = a2 / fmaxf(no * lnorm[2], EPSV);
        }
    }
    __syncthreads();
    if (tid < TOPN) {
        float bv = sim[0][tid]; int bi = 0;
        for (int o = 1; o < OBJ; o++) { float s = sim[o][tid]; if (s > bv) { bv = s; bi = o; } }
        best[tid] = bi;
    }
    __syncthreads();

    const float* q = q3 + (size_t)b * CAND_ALL;
    const float* cf = cand_feat + ((size_t)(b * IMG + i)) * FEAT;
    float part = 0.f;
    for (int j = tid; j < FEAT; j += 256) part += cf[j] * q[j];
    for (int tt = 0; tt < TOPN; tt++) {
        const float* row = obase + (size_t)best[tt] * Dd;
        const float* qs = q + FEAT + tt * (Dd + 7);
        for (int j = tid; j < Dd; j += 256) part += row[j] * qs[j];
    }
    red[tid] = part; __syncthreads();
    for (int off = 128; off > 0; off >>= 1) { if (tid < off) red[tid] += red[tid + off]; __syncthreads(); }
    if (tid == 0) {
        float s = red[0];
        const float* cr = crel_in + ((size_t)(b * IMG + i)) * 6;
        for (int tt = 0; tt < TOPN; tt++) {
            const float* qs = q + FEAT + tt * (Dd + 7);
            float rm = rmask[b * TOPN + tt];
            float lor = 0.f;
            #pragma unroll
            for (int r = 0; r < 6; r++) {
                lor += cr[r] * lrel[(b * TOPN + tt) * 6 + r];
                s += cr[r] * rm * qs[Dd + r];
            }
            s += lor * qs[Dd + 6];
        }
        logit[b * IMG + i] = s;
    }
}

// ---------------- launch ----------------
extern "C" void kernel_launch(void* const* d_in, const int* in_sizes, int n_in,
                              void* d_out, int out_size)
{
    const float* action     = (const float*)d_in[0];
    const float* feature    = (const float*)d_in[1];
    const float* cand_feat  = (const float*)d_in[2];
    const float* prev_h1    = (const float*)d_in[3];
    const float* c_0        = (const float*)d_in[4];
    const float* ctx        = (const float*)d_in[5];
    const float* s_0        = (const float*)d_in[6];
    const float* land       = (const float*)d_in[7];   // [B,CFG,LM,D] == [B,M,D]
    const float* cand_obj   = (const float*)d_in[8];   // [B,IMG,OBJ,D]
    const float* lmask      = (const float*)d_in[9];   // [B,CFG,LM] == [B,M]
    const float* lrel_in    = (const float*)d_in[10];  // [B,M,6]
    const float* rmask_in   = (const float*)d_in[11];  // [B,M]
    const float* crel_in    = (const float*)d_in[12];  // [B,IMG,6]
    const float* pano_obj   = (const float*)d_in[13];  // [B,PANO,OBJ,D]
    const float* embW       = (const float*)d_in[14];
    const float* embb       = (const float*)d_in[15];
    const float* W_ih       = (const float*)d_in[16];
    const float* W_hh       = (const float*)d_in[17];
    const float* b_lstm     = (const float*)d_in[18];
    const float* feat_in_W  = (const float*)d_in[19];
    const float* att_in_W   = (const float*)d_in[20];
    const float* att_out_W  = (const float*)d_in[21];
    const float* cand_in_W  = (const float*)d_in[22];
    // d_in[23] = ctx_mask: all-false -> no-op in reference, ignored.

    float* out   = (float*)d_out;
    float* h1    = out;                          // [B,H]
    float* c1    = out + Bz * Hh;                // [B,H]
    float* logit = out + 2 * Bz * Hh;            // [B,IMG]
    float* ht    = out + 2 * Bz * Hh + Bz * IMG; // [B,H]
    float* ctxa  = ht + Bz * Hh;                 // [B,CFG]

    // device-global scratch addresses
    int   *p_top, *p_ctop;
    float *p_lsel, *p_lnorm, *p_cland, *p_clnorm, *p_lrel, *p_rmask, *p_psim;
    float *p_qf, *p_ap, *p_x, *p_g, *p_q2, *p_cat, *p_qc;
    cudaGetSymbolAddress((void**)&p_top,    g_top_idx);
    cudaGetSymbolAddress((void**)&p_ctop,   g_ctop);
    cudaGetSymbolAddress((void**)&p_lsel,   g_land_sel);
    cudaGetSymbolAddress((void**)&p_lnorm,  g_land_norm);
    cudaGetSymbolAddress((void**)&p_cland,  g_cland);
    cudaGetSymbolAddress((void**)&p_clnorm, g_cland_norm);
    cudaGetSymbolAddress((void**)&p_lrel,   g_lrel);
    cudaGetSymbolAddress((void**)&p_rmask,  g_rmask);
    cudaGetSymbolAddress((void**)&p_psim,   g_pano_sim);
    cudaGetSymbolAddress((void**)&p_qf,     g_q_feat);
    cudaGetSymbolAddress((void**)&p_ap,     g_attn_p);
    cudaGetSymbolAddress((void**)&p_x,      g_x);
    cudaGetSymbolAddress((void**)&p_g,      g_gates);
    cudaGetSymbolAddress((void**)&p_q2,     g_q2);
    cudaGetSymbolAddress((void**)&p_cat,    g_cat);
    cudaGetSymbolAddress((void**)&p_qc,     g_q_cand);

    // 1. top-3 landmark selection from s_0
    k_select<<<Bz, 128>>>(s_0, lmask, land, p_top, p_lsel, p_lnorm,
                          nullptr, nullptr, nullptr, nullptr, 0);
    // 2. pano cosine argmax + gather
    k_pano<<<dim3(PANO, Bz), 256>>>(pano_obj, p_lsel, p_lnorm, p_psim);
    // 3. action embedding -> x[:, :64]
    k_actemb<<<Bz, EMB>>>(action, embW, embb, p_x);
    // 4. q_feat = prev_h1 @ feat_in_W
    sgemm_tn<<<dim3((FEAT_ALL + 31) / 32, Bz / 8), dim3(32, 8)>>>(
        prev_h1, feat_in_W, nullptr, p_qf, Hh, FEAT_ALL, 0, 0);
    // 5/6. feature attention
    k_attn_a<<<Bz, 256>>>(feature, p_psim, p_qf, p_ap);
    k_attn_feat<<<dim3((FEAT_ALL + 127) / 128, Bz), 128>>>(feature, p_psim, p_ap, p_x);
    // 7. LSTM gates: x@W_ih + b ; += prev_h1@W_hh
    sgemm_tn<<<dim3(G4 / 32, Bz / 8), dim3(32, 8)>>>(p_x, W_ih, b_lstm, p_g, XDIM, G4, 0, 0);
    sgemm_tn<<<dim3(G4 / 32, Bz / 8), dim3(32, 8)>>>(prev_h1, W_hh, nullptr, p_g, Hh, G4, 0, 1);
    // 8. cell
    k_cell<<<(Bz * Hh + 255) / 256, 256>>>(p_g, c_0, h1, c1);
    // 9. q2 = h1 @ att_in_W
    sgemm_tn<<<dim3(Hh / 32, Bz / 8), dim3(32, 8)>>>(h1, att_in_W, nullptr, p_q2, Hh, Hh, 0, 0);
    // 10. ctx attention
    k_ctx<<<Bz, 512>>>(ctx, p_q2, h1, ctxa, p_cat);
    // 11. h_tilde = tanh([wctx,h1] @ att_out_W)
    sgemm_tn<<<dim3(Hh / 32, Bz / 8), dim3(32, 8)>>>(p_cat, att_out_W, nullptr, ht, 2 * Hh, Hh, 1, 0);
    // 12. top-3 from ctx_attn + relation gathers
    k_select<<<Bz, 128>>>(ctxa, lmask, land, p_ctop, p_cland, p_clnorm,
                          lrel_in, rmask_in, p_lrel, p_rmask, 1);
    // 13. q3 = h_tilde @ cand_in_W
    sgemm_tn<<<dim3((CAND_ALL + 31) / 32, Bz / 8), dim3(32, 8)>>>(
        ht, cand_in_W, nullptr, p_qc, Hh, CAND_ALL, 0, 0);
    // 14. candidate argmax + logits
    k_logit<<<dim3(IMG, Bz), 256>>>(cand_obj, p_cland, p_clnorm, cand_feat,
                                    crel_in, p_lrel, p_rmask, p_qc, logit);
}

// round 2
// speedup vs baseline: 2.7666x; 2.7666x over previous
#include <cuda_runtime.h>
#include <math.h>

// ---------------- problem constants ----------------
#define Bz   64
#define PANO 36
#define OBJ  36
#define CFG  16
#define LM   8
#define IMG  32
#define Dd   300
#define Hh   512
#define EMB  64
#define ANG  128
#define FEAT 2176
#define TOPN 3
#define Mm   128          // CFG*LM
#define FEAT_ALL 3076     // FEAT + TOPN*D
#define XDIM 3140         // EMB + FEAT_ALL
#define G4   2048         // 4*H
#define CAND_ALL 3097     // FEAT + TOPN*7 + TOPN*D
#define EPSV 1e-8f

// ---------------- scratch (static device globals; no allocation) ----------------
__device__ int   g_top_idx[Bz * TOPN];
__device__ int   g_ctop[Bz * TOPN];
__device__ float g_land_sel[Bz * TOPN * Dd];
__device__ float g_land_norm[Bz * TOPN];
__device__ float g_cland[Bz * TOPN * Dd];
__device__ float g_cland_norm[Bz * TOPN];
__device__ float g_lrel[Bz * TOPN * 6];
__device__ float g_rmask[Bz * TOPN];
__device__ float g_pano_sim[(size_t)Bz * PANO * TOPN * Dd];  // 8.3 MB
__device__ float g_q_feat[Bz * FEAT_ALL];
__device__ float g_attn_p[Bz * PANO];
__device__ float g_x[Bz * XDIM];
__device__ float g_q2[Bz * Hh];
__device__ float g_cat[Bz * 2 * Hh];
__device__ float g_q_cand[Bz * CAND_ALL];
__device__ float g_part[12 * Bz * G4];   // split-K partials (max: 12 x 64 x 2048)

// ---------------- helpers ----------------
__device__ __forceinline__ float warp_sum(float v) {
    #pragma unroll
    for (int off = 16; off > 0; off >>= 1) v += __shfl_xor_sync(0xffffffffu, v, off);
    return v;
}
__device__ __forceinline__ float sigmoidf(float x) { return 1.0f / (1.0f + expf(-x)); }

// ================= tiled GEMM: part[s][b][j] = A[b, kbeg:kend] @ W[kbeg:kend, j] ==========
// A: [64, K] row-major (K % 4 == 0). W: [K, N] row-major.
// Block: 256 threads, computes 64(B) x 64(N) tile for one K-split.
// VECW: float4 loads/stores on W/partials (requires N % 4 == 0).
template<bool VECW>
__global__ void gemm64(const float* __restrict__ A, const float* __restrict__ W,
                       float* __restrict__ part, int K, int N, int Kc, int split_base)
{
    __shared__ float As[32][65];   // [k][b] transposed, padded: conflict-free
    __shared__ float Ws[32][64];   // [k][j]
    const int jtile = blockIdx.x * 64;
    const int kbeg = blockIdx.y * Kc;
    const int kend = min(kbeg + Kc, K);
    const int tid = threadIdx.x;
    const int tx = tid & 15, ty = tid >> 4;

    float acc[4][4] = {};

    for (int k0 = kbeg; k0 < kend; k0 += 32) {
        // --- load A tile: 64 rows x 32 k (512 float4, 2 per thread) ---
        {
            int idx = tid;
            #pragma unroll
            for (int r = 0; r < 2; r++, idx += 256) {
                int row = idx >> 3, kq = idx & 7;
                int kg = k0 + kq * 4;
                float4 v = make_float4(0.f, 0.f, 0.f, 0.f);
                if (kg < kend) v = *(const float4*)(A + (size_t)row * K + kg);
                As[kq * 4 + 0][row] = v.x;
                As[kq * 4 + 1][row] = v.y;
                As[kq * 4 + 2][row] = v.z;
                As[kq * 4 + 3][row] = v.w;
            }
        }
        // --- load W tile: 32 k x 64 j ---
        if (VECW) {
            int idx = tid;
            #pragma unroll
            for (int r = 0; r < 2; r++, idx += 256) {
                int kk = idx >> 4, jq = idx & 15;
                int kg = k0 + kk, jg = jtile + jq * 4;
                float4 v = make_float4(0.f, 0.f, 0.f, 0.f);
                if (kg < kend && jg < N) v = *(const float4*)(W + (size_t)kg * N + jg);
                *(float4*)&Ws[kk][jq * 4] = v;
            }
        } else {
            #pragma unroll
            for (int r = 0; r < 8; r++) {
                int idx = tid + r * 256;
                int kk = idx >> 6, jj = idx & 63;
                int kg = k0 + kk, jg = jtile + jj;
                Ws[kk][jj] = (kg < kend && jg < N) ? W[(size_t)kg * N + jg] : 0.f;
            }
        }
        __syncthreads();

        #pragma unroll
        for (int kk = 0; kk < 32; kk++) {
            float4 w = *(const float4*)&Ws[kk][tx * 4];
            float a0 = As[kk][ty * 4 + 0];
            float a1 = As[kk][ty * 4 + 1];
            float a2 = As[kk][ty * 4 + 2];
            float a3 = As[kk][ty * 4 + 3];
            acc[0][0] += a0 * w.x; acc[0][1] += a0 * w.y; acc[0][2] += a0 * w.z; acc[0][3] += a0 * w.w;
            acc[1][0] += a1 * w.x; acc[1][1] += a1 * w.y; acc[1][2] += a1 * w.z; acc[1][3] += a1 * w.w;
            acc[2][0] += a2 * w.x; acc[2][1] += a2 * w.y; acc[2][2] += a2 * w.z; acc[2][3] += a2 * w.w;
            acc[3][0] += a3 * w.x; acc[3][1] += a3 * w.y; acc[3][2] += a3 * w.z; acc[3][3] += a3 * w.w;
        }
        __syncthreads();
    }

    float* p = part + (size_t)(split_base + blockIdx.y) * (Bz * (size_t)N);
    int j = jtile + tx * 4;
    #pragma unroll
    for (int i = 0; i < 4; i++) {
        int b = ty * 4 + i;
        if (VECW) {
            if (j < N)
                *(float4*)(p + (size_t)b * N + j) =
                    make_float4(acc[i][0], acc[i][1], acc[i][2], acc[i][3]);
        } else {
            #pragma unroll
            for (int q = 0; q < 4; q++)
                if (j + q < N) p[(size_t)b * N + j + q] = acc[i][q];
        }
    }
}

// combine split-K partials: out[b,j] = act( sum_s part[s][b][j] + bias[j] )
__global__ void k_combine(const float* __restrict__ part, const float* __restrict__ bias,
                          float* __restrict__ out, int N, int S, int act)
{
    int idx = blockIdx.x * 256 + threadIdx.x;
    if (idx >= Bz * N) return;
    int j = idx % N;
    float s = 0.f;
    for (int ss = 0; ss < S; ss++) s += part[(size_t)ss * Bz * N + idx];
    if (bias) s += bias[j];
    if (act) s = tanhf(s);
    out[idx] = s;
}

// combine gates partials (S=12, N=2048) + bias + LSTM cell
__global__ void k_combine_cell(const float* __restrict__ part, const float* __restrict__ bias,
                               const float* __restrict__ c0,
                               float* __restrict__ h1, float* __restrict__ c1)
{
    int idx = blockIdx.x * 256 + threadIdx.x;
    if (idx >= Bz * Hh) return;
    int b = idx / Hh, h = idx % Hh;
    float g0 = bias[h], g1 = bias[Hh + h], g2 = bias[2 * Hh + h], g3 = bias[3 * Hh + h];
    #pragma unroll 4
    for (int ss = 0; ss < 12; ss++) {
        const float* p = part + (size_t)ss * Bz * G4 + (size_t)b * G4;
        g0 += p[h]; g1 += p[Hh + h]; g2 += p[2 * Hh + h]; g3 += p[3 * Hh + h];
    }
    float ig = sigmoidf(g0), fg = sigmoidf(g1), gg = tanhf(g2), og = sigmoidf(g3);
    float c = fg * c0[idx] + ig * gg;
    c1[idx] = c;
    h1[idx] = og * tanhf(c);
}

// ---------------- K_select: top-3 of (weights x landmark_mask), gather land rows + norms ---------
__global__ void k_select(const float* __restrict__ weights, const float* __restrict__ lmask,
                         const float* __restrict__ land, int* __restrict__ out_idx,
                         float* __restrict__ out_rows, float* __restrict__ out_norm,
                         const float* __restrict__ lrel_src, const float* __restrict__ rmask_src,
                         float* __restrict__ out_lrel, float* __restrict__ out_rmask, int mode)
{
    int b = blockIdx.x;
    int t = threadIdx.x;  // 128
    __shared__ float v[Mm];
    __shared__ int bidx[TOPN];
    __shared__ float red[128];

    v[t] = weights[b * CFG + (t >> 3)] * lmask[b * Mm + t];
    __syncthreads();
    if (t == 0) {
        for (int rep = 0; rep < TOPN; rep++) {
            float bv = v[0]; int bi = 0;
            for (int m = 1; m < Mm; m++) { float x = v[m]; if (x > bv) { bv = x; bi = m; } }
            bidx[rep] = bi; v[bi] = -3.4e38f;
        }
    }
    __syncthreads();
    if (t < TOPN) out_idx[b * TOPN + t] = bidx[t];

    for (int tt = 0; tt < TOPN; tt++) {
        int m = bidx[tt];
        const float* src = land + ((size_t)(b * Mm + m)) * Dd;
        float part = 0.f;
        for (int j = t; j < Dd; j += 128) {
            float x = src[j];
            out_rows[((size_t)(b * TOPN + tt)) * Dd + j] = x;
            part += x * x;
        }
        red[t] = part; __syncthreads();
        for (int off = 64; off > 0; off >>= 1) { if (t < off) red[t] += red[t + off]; __syncthreads(); }
        if (t == 0) out_norm[b * TOPN + tt] = sqrtf(red[0]);
        __syncthreads();
    }

    if (mode == 1) {
        if (t < TOPN * 6) {
            int tt = t / 6, r = t % 6;
            out_lrel[(b * TOPN + tt) * 6 + r] = lrel_src[((size_t)(b * Mm + bidx[tt])) * 6 + r];
        }
        if (t < TOPN) out_rmask[b * TOPN + t] = rmask_src[b * Mm + bidx[t]];
    }
}

// ---------------- K_pano: cosine argmax over 36 objects vs 3 selected land rows; gather rows ------
__global__ void k_pano(const float* __restrict__ pano_obj, const float* __restrict__ land_sel,
                       const float* __restrict__ land_norm, float* __restrict__ pano_sim)
{
    int b = blockIdx.y, p = blockIdx.x;
    int tid = threadIdx.x;              // 256
    int warp = tid >> 5, lane = tid & 31;
    __shared__ float land[TOPN][Dd];
    __shared__ float lnorm[TOPN];
    __shared__ float sim[OBJ][TOPN];
    __shared__ int best[TOPN];

    for (int idx = tid; idx < TOPN * Dd; idx += 256)
        land[idx / Dd][idx % Dd] = land_sel[(size_t)b * TOPN * Dd + idx];
    if (tid < TOPN) lnorm[tid] = land_norm[b * TOPN + tid];
    __syncthreads();

    const float* obase = pano_obj + ((size_t)(b * PANO + p)) * OBJ * Dd;
    for (int o = warp; o < OBJ; o += 8) {
        const float* row = obase + (size_t)o * Dd;
        float a0 = 0, a1 = 0, a2 = 0, an = 0;
        for (int j = lane; j < Dd; j += 32) {
            float x = row[j];
            a0 += x * land[0][j]; a1 += x * land[1][j]; a2 += x * land[2][j]; an += x * x;
        }
        a0 = warp_sum(a0); a1 = warp_sum(a1); a2 = warp_sum(a2); an = warp_sum(an);
        if (lane == 0) {
            float no = sqrtf(an);
            sim[o][0] = a0 / fmaxf(no * lnorm[0], EPSV);
            sim[o][1] = a1 / fmaxf(no * lnorm[1], EPSV);
            sim[o][2] = a2 / fmaxf(no * lnorm[2], EPSV);
        }
    }
    __syncthreads();
    if (tid < TOPN) {
        float bv = sim[0][tid]; int bi = 0;
        for (int o = 1; o < OBJ; o++) { float s = sim[o][tid]; if (s > bv) { bv = s; bi = o; } }
        best[tid] = bi;
    }
    __syncthreads();
    for (int tt = 0; tt < TOPN; tt++) {
        const float* row = obase + (size_t)best[tt] * Dd;
        float* dst = pano_sim + (((size_t)(b * PANO + p)) * TOPN + tt) * Dd;
        for (int j = tid; j < Dd; j += 256) dst[j] = row[j];
    }
}

// ---------------- K_actemb ----------------
__global__ void k_actemb(const float* __restrict__ action, const float* __restrict__ embW,
                         const float* __restrict__ embb, float* __restrict__ x)
{
    int b = blockIdx.x, e = threadIdx.x;  // 64 threads
    float acc = 0.f;
    #pragma unroll 4
    for (int a = 0; a < ANG; a++) acc += action[b * ANG + a] * embW[a * EMB + e];
    x[(size_t)b * XDIM + e] = tanhf(acc + embb[e]);
}

// ---------------- K_attn_a: attention logits + softmax over 36 pano views ----------------
__global__ void k_attn_a(const float* __restrict__ feature, const float* __restrict__ pano_sim,
                         const float* __restrict__ q, float* __restrict__ attn_p)
{
    int b = blockIdx.x;
    int tid = threadIdx.x, warp = tid >> 5, lane = tid & 31; // 256 threads
    __shared__ float aval[PANO];
    __shared__ float pvals[PANO];
    const float* qb = q + (size_t)b * FEAT_ALL;
    for (int s = warp; s < PANO; s += 8) {
        const float* f  = feature  + ((size_t)(b * PANO + s)) * FEAT;
        const float* ps = pano_sim + ((size_t)(b * PANO + s)) * TOPN * Dd;
        float acc = 0.f;
        for (int j = lane; j < FEAT; j += 32) acc += f[j] * qb[j];
        for (int j = lane; j < TOPN * Dd; j += 32) acc += ps[j] * qb[FEAT + j];
        acc = warp_sum(acc);
        if (lane == 0) aval[s] = acc;
    }
    __syncthreads();
    if (tid == 0) {
        float mx = aval[0];
        for (int s = 1; s < PANO; s++) mx = fmaxf(mx, aval[s]);
        float sum = 0.f;
        for (int s = 0; s < PANO; s++) { float e = expf(aval[s] - mx); pvals[s] = e; sum += e; }
        float inv = 1.0f / sum;
        for (int s = 0; s < PANO; s++) pvals[s] *= inv;
    }
    __syncthreads();
    if (tid < PANO) attn_p[b * PANO + tid] = pvals[tid];
}

// ---------------- K_attn_feat ----------------
__global__ void k_attn_feat(const float* __restrict__ feature, const float* __restrict__ pano_sim,
                            const float* __restrict__ attn_p, float* __restrict__ x)
{
    int b = blockIdx.y;
    int j = blockIdx.x * 128 + threadIdx.x;
    if (j >= FEAT_ALL) return;
    float acc = 0.f;
    if (j < FEAT) {
        #pragma unroll 4
        for (int s = 0; s < PANO; s++)
            acc += attn_p[b * PANO + s] * feature[((size_t)(b * PANO + s)) * FEAT + j];
    } else {
        int jj = j - FEAT;
        #pragma unroll 4
        for (int s = 0; s < PANO; s++)
            acc += attn_p[b * PANO + s] * pano_sim[((size_t)(b * PANO + s)) * TOPN * Dd + jj];
    }
    x[(size_t)b * XDIM + EMB + j] = acc;
}

// ---------------- K_ctx: ctx attention (softmax over 16), wctx, build [wctx,h1] ----------------
__global__ void k_ctx(const float* __restrict__ ctx, const float* __restrict__ q2,
                      const float* __restrict__ h1, float* __restrict__ ctx_attn,
                      float* __restrict__ cat)
{
    int b = blockIdx.x;
    int tid = threadIdx.x, warp = tid >> 5, lane = tid & 31; // 512 threads
    __shared__ float lg[CFG];
    __shared__ float pr[CFG];
    {
        int s = warp;
        const float* c = ctx + ((size_t)(b * CFG + s)) * Hh;
        const float* q = q2 + (size_t)b * Hh;
        float acc = 0.f;
        for (int j = lane; j < Hh; j += 32) acc += c[j] * q[j];
        acc = warp_sum(acc);
        if (lane == 0) lg[s] = acc;
    }
    __syncthreads();
    if (tid == 0) {
        float mx = lg[0];
        for (int s = 1; s < CFG; s++) mx = fmaxf(mx, lg[s]);
        float sum = 0.f;
        for (int s = 0; s < CFG; s++) { float e = expf(lg[s] - mx); pr[s] = e; sum += e; }
        float inv = 1.0f / sum;
        for (int s = 0; s < CFG; s++) pr[s] *= inv;
    }
    __syncthreads();
    if (tid < CFG) ctx_attn[b * CFG + tid] = pr[tid];
    float acc = 0.f;
    #pragma unroll
    for (int s = 0; s < CFG; s++) acc += pr[s] * ctx[((size_t)(b * CFG + s)) * Hh + tid];
    cat[(size_t)b * 2 * Hh + tid] = acc;
    cat[(size_t)b * 2 * Hh + Hh + tid] = h1[(size_t)b * Hh + tid];
}

// ---------------- K_logit: candidate cosine argmax (3 rows) + final logit dot ----------------
__global__ void k_logit(const float* __restrict__ cand_obj, const float* __restrict__ cland,
                        const float* __restrict__ cland_norm, const float* __restrict__ cand_feat,
                        const float* __restrict__ crel_in, const float* __restrict__ lrel,
                        const float* __restrict__ rmask, const float* __restrict__ q3,
                        float* __restrict__ logit)
{
    int b = blockIdx.y, i = blockIdx.x;
    int tid = threadIdx.x, warp = tid >> 5, lane = tid & 31; // 256 threads
    __shared__ float land[TOPN][Dd];
    __shared__ float lnorm[TOPN];
    __shared__ float sim[OBJ][TOPN];
    __shared__ int best[TOPN];
    __shared__ float red[256];

    for (int idx = tid; idx < TOPN * Dd; idx += 256)
        land[idx / Dd][idx % Dd] = cland[(size_t)b * TOPN * Dd + idx];
    if (tid < TOPN) lnorm[tid] = cland_norm[b * TOPN + tid];
    __syncthreads();

    const float* obase = cand_obj + ((size_t)(b * IMG + i)) * OBJ * Dd;
    for (int o = warp; o < OBJ; o += 8) {
        const float* row = obase + (size_t)o * Dd;
        float a0 = 0, a1 = 0, a2 = 0, an = 0;
        for (int j = lane; j < Dd; j += 32) {
            float x = row[j];
            a0 += x * land[0][j]; a1 += x * land[1][j]; a2 += x * land[2][j]; an += x * x;
        }
        a0 = warp_sum(a0); a1 = warp_sum(a1); a2 = warp_sum(a2); an = warp_sum(an);
        if (lane == 0) {
            float no = sqrtf(an);
            sim[o][0] = a0 / fmaxf(no * lnorm[0], EPSV);
            sim[o][1] = a1 / fmaxf(no * lnorm[1], EPSV);
            sim[o][2] = a2 / fmaxf(no * lnorm[2], EPSV);
        }
    }
    __syncthreads();
    if (tid < TOPN) {
        float bv = sim[0][tid]; int bi = 0;
        for (int o = 1; o < OBJ; o++) { float s = sim[o][tid]; if (s > bv) { bv = s; bi = o; } }
        best[tid] = bi;
    }
    __syncthreads();

    const float* q = q3 + (size_t)b * CAND_ALL;
    const float* cf = cand_feat + ((size_t)(b * IMG + i)) * FEAT;
    float part = 0.f;
    for (int j = tid; j < FEAT; j += 256) part += cf[j] * q[j];
    for (int tt = 0; tt < TOPN; tt++) {
        const float* row = obase + (size_t)best[tt] * Dd;
        const float* qs = q + FEAT + tt * (Dd + 7);
        for (int j = tid; j < Dd; j += 256) part += row[j] * qs[j];
    }
    red[tid] = part; __syncthreads();
    for (int off = 128; off > 0; off >>= 1) { if (tid < off) red[tid] += red[tid + off]; __syncthreads(); }
    if (tid == 0) {
        float s = red[0];
        const float* cr = crel_in + ((size_t)(b * IMG + i)) * 6;
        for (int tt = 0; tt < TOPN; tt++) {
            const float* qs = q + FEAT + tt * (Dd + 7);
            float rm = rmask[b * TOPN + tt];
            float lor = 0.f;
            #pragma unroll
            for (int r = 0; r < 6; r++) {
                lor += cr[r] * lrel[(b * TOPN + tt) * 6 + r];
                s += cr[r] * rm * qs[Dd + r];
            }
            s += lor * qs[Dd + 6];
        }
        logit[b * IMG + i] = s;
    }
}

// ---------------- launch ----------------
extern "C" void kernel_launch(void* const* d_in, const int* in_sizes, int n_in,
                              void* d_out, int out_size)
{
    const float* action     = (const float*)d_in[0];
    const float* feature    = (const float*)d_in[1];
    const float* cand_feat  = (const float*)d_in[2];
    const float* prev_h1    = (const float*)d_in[3];
    const float* c_0        = (const float*)d_in[4];
    const float* ctx        = (const float*)d_in[5];
    const float* s_0        = (const float*)d_in[6];
    const float* land       = (const float*)d_in[7];
    const float* cand_obj   = (const float*)d_in[8];
    const float* lmask      = (const float*)d_in[9];
    const float* lrel_in    = (const float*)d_in[10];
    const float* rmask_in   = (const float*)d_in[11];
    const float* crel_in    = (const float*)d_in[12];
    const float* pano_obj   = (const float*)d_in[13];
    const float* embW       = (const float*)d_in[14];
    const float* embb       = (const float*)d_in[15];
    const float* W_ih       = (const float*)d_in[16];
    const float* W_hh       = (const float*)d_in[17];
    const float* b_lstm     = (const float*)d_in[18];
    const float* feat_in_W  = (const float*)d_in[19];
    const float* att_in_W   = (const float*)d_in[20];
    const float* att_out_W  = (const float*)d_in[21];
    const float* cand_in_W  = (const float*)d_in[22];
    // d_in[23] = ctx_mask: all-false -> identity

    float* out   = (float*)d_out;
    float* h1    = out;
    float* c1    = out + Bz * Hh;
    float* logit = out + 2 * Bz * Hh;
    float* ht    = out + 2 * Bz * Hh + Bz * IMG;
    float* ctxa  = ht + Bz * Hh;

    int   *p_top, *p_ctop;
    float *p_lsel, *p_lnorm, *p_cland, *p_clnorm, *p_lrel, *p_rmask, *p_psim;
    float *p_qf, *p_ap, *p_x, *p_q2, *p_cat, *p_qc, *p_part;
    cudaGetSymbolAddress((void**)&p_top,    g_top_idx);
    cudaGetSymbolAddress((void**)&p_ctop,   g_ctop);
    cudaGetSymbolAddress((void**)&p_lsel,   g_land_sel);
    cudaGetSymbolAddress((void**)&p_lnorm,  g_land_norm);
    cudaGetSymbolAddress((void**)&p_cland,  g_cland);
    cudaGetSymbolAddress((void**)&p_clnorm, g_cland_norm);
    cudaGetSymbolAddress((void**)&p_lrel,   g_lrel);
    cudaGetSymbolAddress((void**)&p_rmask,  g_rmask);
    cudaGetSymbolAddress((void**)&p_psim,   g_pano_sim);
    cudaGetSymbolAddress((void**)&p_qf,     g_q_feat);
    cudaGetSymbolAddress((void**)&p_ap,     g_attn_p);
    cudaGetSymbolAddress((void**)&p_x,      g_x);
    cudaGetSymbolAddress((void**)&p_q2,     g_q2);
    cudaGetSymbolAddress((void**)&p_cat,    g_cat);
    cudaGetSymbolAddress((void**)&p_qc,     g_q_cand);
    cudaGetSymbolAddress((void**)&p_part,   g_part);

    // 1. top-3 landmark selection from s_0
    k_select<<<Bz, 128>>>(s_0, lmask, land, p_top, p_lsel, p_lnorm,
                          nullptr, nullptr, nullptr, nullptr, 0);
    // 2. pano cosine argmax + gather
    k_pano<<<dim3(PANO, Bz), 256>>>(pano_obj, p_lsel, p_lnorm, p_psim);
    // 3. action embedding -> x[:, :64]
    k_actemb<<<Bz, EMB>>>(action, embW, embb, p_x);
    // 4. q_feat = prev_h1 @ feat_in_W  (K=512, N=3076, split 4)
    gemm64<true><<<dim3(49, 4), 256>>>(prev_h1, feat_in_W, p_part, Hh, FEAT_ALL, 128, 0);
    k_combine<<<(Bz * FEAT_ALL + 255) / 256, 256>>>(p_part, nullptr, p_qf, FEAT_ALL, 4, 0);
    // 5/6. feature attention
    k_attn_a<<<Bz, 256>>>(feature, p_psim, p_qf, p_ap);
    k_attn_feat<<<dim3((FEAT_ALL + 127) / 128, Bz), 128>>>(feature, p_psim, p_ap, p_x);
    // 7. LSTM gates: x@W_ih (splits 0..7) + prev_h1@W_hh (splits 8..11), fused cell
    gemm64<true><<<dim3(32, 8), 256>>>(p_x, W_ih, p_part, XDIM, G4, 416, 0);
    gemm64<true><<<dim3(32, 4), 256>>>(prev_h1, W_hh, p_part, Hh, G4, 128, 8);
    k_combine_cell<<<(Bz * Hh + 255) / 256, 256>>>(p_part, b_lstm, c_0, h1, c1);
    // 9. q2 = h1 @ att_in_W  (K=512, N=512, split 16)
    gemm64<true><<<dim3(8, 16), 256>>>(h1, att_in_W, p_part, Hh, Hh, 32, 0);
    k_combine<<<(Bz * Hh + 255) / 256, 256>>>(p_part, nullptr, p_q2, Hh, 16, 0);
    // 10. ctx attention
    k_ctx<<<Bz, 512>>>(ctx, p_q2, h1, ctxa, p_cat);
    // 11. h_tilde = tanh([wctx,h1] @ att_out_W)  (K=1024, N=512, split 16)
    gemm64<true><<<dim3(8, 16), 256>>>(p_cat, att_out_W, p_part, 2 * Hh, Hh, 64, 0);
    k_combine<<<(Bz * Hh + 255) / 256, 256>>>(p_part, nullptr, ht, Hh, 16, 1);
    // 12. top-3 from ctx_attn + relation gathers
    k_select<<<Bz, 128>>>(ctxa, lmask, land, p_ctop, p_cland, p_clnorm,
                          lrel_in, rmask_in, p_lrel, p_rmask, 1);
    // 13. q3 = h_tilde @ cand_in_W  (K=512, N=3097 -> scalar W path, split 4)
    gemm64<false><<<dim3(49, 4), 256>>>(ht, cand_in_W, p_part, Hh, CAND_ALL, 128, 0);
    k_combine<<<(Bz * CAND_ALL + 255) / 256, 256>>>(p_part, nullptr, p_qc, CAND_ALL, 4, 0);
    // 14. candidate argmax + logits
    k_logit<<<dim3(IMG, Bz), 256>>>(cand_obj, p_cland, p_clnorm, cand_feat,
                                    crel_in, p_lrel, p_rmask, p_qc, logit);
}

// round 4
// speedup vs baseline: 3.4951x; 1.2633x over previous
#include <cuda_runtime.h>
#include <math.h>

// ---------------- problem constants ----------------
#define Bz   64
#define PANO 36
#define OBJ  36
#define CFG  16
#define LM   8
#define IMG  32
#define Dd   300
#define Hh   512
#define EMB  64
#define ANG  128
#define FEAT 2176
#define TOPN 3
#define Mm   128
#define FEAT_ALL 3076     // FEAT + TOPN*D
#define XDIM 3140         // EMB + FEAT_ALL
#define G4   2048         // 4*H
#define CAND_ALL 3097     // FEAT + TOPN*7 + TOPN*D
#define CAND_PAD 3104     // padded to /4
#define EPSV 1e-8f

#define F4A  769          // FEAT_ALL/4
#define F4F  544          // FEAT/4
#define F4P  225          // TOPN*Dd/4
#define D4   75           // Dd/4

// ---------------- scratch ----------------
__device__ int   g_top_idx[Bz * TOPN];
__device__ int   g_ctop[Bz * TOPN];
__device__ float g_land_sel[Bz * TOPN * Dd];
__device__ float g_land_norm[Bz * TOPN];
__device__ float g_cland[Bz * TOPN * Dd];
__device__ float g_cland_norm[Bz * TOPN];
__device__ float g_lrel[Bz * TOPN * 6];
__device__ float g_rmask[Bz * TOPN];
__device__ float g_pano_sim[(size_t)Bz * PANO * TOPN * Dd];
__device__ float g_attn_p[Bz * PANO];
__device__ float g_x[Bz * XDIM];
__device__ float g_cat[Bz * 2 * Hh];
__device__ float g_q_cand[Bz * CAND_PAD];
__device__ float g_part[2097152];   // split-K partials (max 14*64*2048 = 1.835M floats)

// ---------------- helpers ----------------
__device__ __forceinline__ float warp_sum(float v) {
    #pragma unroll
    for (int off = 16; off > 0; off >>= 1) v += __shfl_xor_sync(0xffffffffu, v, off);
    return v;
}
__device__ __forceinline__ float sigmoidf(float x) { return 1.0f / (1.0f + expf(-x)); }
__device__ __forceinline__ float dot4(float4 a, float4 b) {
    return a.x * b.x + a.y * b.y + a.z * b.z + a.w * b.w;
}
__device__ __forceinline__ float4 f4add(float4 a, float4 b) {
    return make_float4(a.x + b.x, a.y + b.y, a.z + b.z, a.w + b.w);
}

// ================= GEMM: part[s][b][j](padded Np) = A[b, kbeg:kend] @ W[kbeg:kend, j] =========
// A [64,K] row-major (K%4==0, rows 16B aligned). W [K,N] row-major.
// Block: 256 threads -> 64(B) x 128(N) tile. Micro: 4(B) x 8(N). Double-buffered.
template<bool VECW>
__global__ void gemm64v(const float* __restrict__ A, const float* __restrict__ W,
                        float* __restrict__ part, int K, int N, int Np, int Kc, int split_base)
{
    __shared__ float As[2][32][64];
    __shared__ float Ws[2][32][128];
    const int jtile = blockIdx.x * 128;
    const int kbeg = blockIdx.y * Kc;
    const int kend = min(kbeg + Kc, K);
    const int tid = threadIdx.x;
    const int tx = tid & 15, ty = tid >> 4;
    const int nk = (kend - kbeg + 31) >> 5;

    float4 stA[2];
    float4 stW4[4];
    float  stWs[16];

    const int arow0 = tid >> 3, akq = tid & 7;

    auto loadRegs = [&](int k0) {
        #pragma unroll
        for (int r = 0; r < 2; r++) {
            int row = arow0 + r * 32;
            int kg = k0 + akq * 4;
            float4 v = make_float4(0.f, 0.f, 0.f, 0.f);
            if (kg < kend) v = *(const float4*)(A + (size_t)row * K + kg);
            stA[r] = v;
        }
        if (VECW) {
            #pragma unroll
            for (int r = 0; r < 4; r++) {
                int idx = tid + r * 256;
                int kk = idx >> 5, jq = idx & 31;
                int kg = k0 + kk, jg = jtile + jq * 4;
                float4 v = make_float4(0.f, 0.f, 0.f, 0.f);
                if (kg < kend && jg < N) v = *(const float4*)(W + (size_t)kg * N + jg);
                stW4[r] = v;
            }
        } else {
            #pragma unroll
            for (int r = 0; r < 16; r++) {
                int idx = tid + r * 256;
                int kk = idx >> 7, jj = idx & 127;
                int kg = k0 + kk, jg = jtile + jj;
                stWs[r] = (kg < kend && jg < N) ? W[(size_t)kg * N + jg] : 0.f;
            }
        }
    };
    auto storeSmem = [&](int buf) {
        #pragma unroll
        for (int r = 0; r < 2; r++) {
            int row = arow0 + r * 32;
            As[buf][akq * 4 + 0][row] = stA[r].x;
            As[buf][akq * 4 + 1][row] = stA[r].y;
            As[buf][akq * 4 + 2][row] = stA[r].z;
            As[buf][akq * 4 + 3][row] = stA[r].w;
        }
        if (VECW) {
            #pragma unroll
            for (int r = 0; r < 4; r++) {
                int idx = tid + r * 256;
                int kk = idx >> 5, jq = idx & 31;
                *(float4*)&Ws[buf][kk][jq * 4] = stW4[r];
            }
        } else {
            #pragma unroll
            for (int r = 0; r < 16; r++) {
                int idx = tid + r * 256;
                int kk = idx >> 7, jj = idx & 127;
                Ws[buf][kk][jj] = stWs[r];
            }
        }
    };

    float acc[4][8] = {};

    loadRegs(kbeg);
    storeSmem(0);
    __syncthreads();

    for (int t = 0; t < nk; t++) {
        int cur = t & 1;
        if (t + 1 < nk) loadRegs(kbeg + (t + 1) * 32);
        #pragma unroll
        for (int kk = 0; kk < 32; kk++) {
            float4 a = *(const float4*)&As[cur][kk][ty * 4];
            float4 b0 = *(const float4*)&Ws[cur][kk][tx * 8];
            float4 b1 = *(const float4*)&Ws[cur][kk][tx * 8 + 4];
            acc[0][0] += a.x * b0.x; acc[0][1] += a.x * b0.y; acc[0][2] += a.x * b0.z; acc[0][3] += a.x * b0.w;
            acc[0][4] += a.x * b1.x; acc[0][5] += a.x * b1.y; acc[0][6] += a.x * b1.z; acc[0][7] += a.x * b1.w;
            acc[1][0] += a.y * b0.x; acc[1][1] += a.y * b0.y; acc[1][2] += a.y * b0.z; acc[1][3] += a.y * b0.w;
            acc[1][4] += a.y * b1.x; acc[1][5] += a.y * b1.y; acc[1][6] += a.y * b1.z; acc[1][7] += a.y * b1.w;
            acc[2][0] += a.z * b0.x; acc[2][1] += a.z * b0.y; acc[2][2] += a.z * b0.z; acc[2][3] += a.z * b0.w;
            acc[2][4] += a.z * b1.x; acc[2][5] += a.z * b1.y; acc[2][6] += a.z * b1.z; acc[2][7] += a.z * b1.w;
            acc[3][0] += a.w * b0.x; acc[3][1] += a.w * b0.y; acc[3][2] += a.w * b0.z; acc[3][3] += a.w * b0.w;
            acc[3][4] += a.w * b1.x; acc[3][5] += a.w * b1.y; acc[3][6] += a.w * b1.z; acc[3][7] += a.w * b1.w;
        }
        if (t + 1 < nk) storeSmem(cur ^ 1);
        __syncthreads();
    }

    float* p = part + (size_t)(split_base + blockIdx.y) * ((size_t)Bz * Np);
    int j0 = jtile + tx * 8;
    #pragma unroll
    for (int i = 0; i < 4; i++) {
        int b = ty * 4 + i;
        if (j0 < N)
            *(float4*)(p + (size_t)b * Np + j0) = make_float4(acc[i][0], acc[i][1], acc[i][2], acc[i][3]);
        if (j0 + 4 < N)
            *(float4*)(p + (size_t)b * Np + j0 + 4) = make_float4(acc[i][4], acc[i][5], acc[i][6], acc[i][7]);
    }
}

// combine: out4[i] = act( sum_s part4[s][i] )
__global__ void k_combine(const float* __restrict__ part, float* __restrict__ out,
                          int count4, int S, int stride4, int act)
{
    int idx = blockIdx.x * 256 + threadIdx.x;
    if (idx >= count4) return;
    const float4* p4 = (const float4*)part;
    float4 s = make_float4(0.f, 0.f, 0.f, 0.f);
    for (int ss = 0; ss < S; ss++) s = f4add(s, p4[(size_t)ss * stride4 + idx]);
    if (act) { s.x = tanhf(s.x); s.y = tanhf(s.y); s.z = tanhf(s.z); s.w = tanhf(s.w); }
    ((float4*)out)[idx] = s;
}

// combine gates partials (S splits, N=2048) + bias + LSTM cell; vectorized
__global__ void k_combine_cell(const float* __restrict__ part, const float* __restrict__ bias,
                               const float* __restrict__ c0,
                               float* __restrict__ h1, float* __restrict__ c1, int S)
{
    int idx = blockIdx.x * 256 + threadIdx.x;   // over Bz*Hh/4 = 8192
    if (idx >= Bz * Hh / 4) return;
    int b = idx >> 7, hq = idx & 127;
    const float4* p4 = (const float4*)part;
    const float4* b4 = (const float4*)bias;
    float4 g0 = b4[hq], g1 = b4[128 + hq], g2 = b4[256 + hq], g3 = b4[384 + hq];
    for (int ss = 0; ss < S; ss++) {
        const float4* pb = p4 + (size_t)(ss * Bz + b) * 512;
        g0 = f4add(g0, pb[hq]);
        g1 = f4add(g1, pb[128 + hq]);
        g2 = f4add(g2, pb[256 + hq]);
        g3 = f4add(g3, pb[384 + hq]);
    }
    float4 c0v = ((const float4*)c0)[idx];
    float4 cc, hh;
    {
        float ig = sigmoidf(g0.x), fg = sigmoidf(g1.x), gg = tanhf(g2.x), og = sigmoidf(g3.x);
        cc.x = fg * c0v.x + ig * gg; hh.x = og * tanhf(cc.x);
    }
    {
        float ig = sigmoidf(g0.y), fg = sigmoidf(g1.y), gg = tanhf(g2.y), og = sigmoidf(g3.y);
        cc.y = fg * c0v.y + ig * gg; hh.y = og * tanhf(cc.y);
    }
    {
        float ig = sigmoidf(g0.z), fg = sigmoidf(g1.z), gg = tanhf(g2.z), og = sigmoidf(g3.z);
        cc.z = fg * c0v.z + ig * gg; hh.z = og * tanhf(cc.z);
    }
    {
        float ig = sigmoidf(g0.w), fg = sigmoidf(g1.w), gg = tanhf(g2.w), og = sigmoidf(g3.w);
        cc.w = fg * c0v.w + ig * gg; hh.w = og * tanhf(cc.w);
    }
    ((float4*)c1)[idx] = cc;
    ((float4*)h1)[idx] = hh;
}

// ---------------- K_select ----------------
__global__ void k_select(const float* __restrict__ weights, const float* __restrict__ lmask,
                         const float* __restrict__ land, int* __restrict__ out_idx,
                         float* __restrict__ out_rows, float* __restrict__ out_norm,
                         const float* __restrict__ lrel_src, const float* __restrict__ rmask_src,
                         float* __restrict__ out_lrel, float* __restrict__ out_rmask, int mode)
{
    int b = blockIdx.x;
    int t = threadIdx.x;  // 128
    __shared__ float v[Mm];
    __shared__ int bidx[TOPN];
    __shared__ float red[128];

    v[t] = weights[b * CFG + (t >> 3)] * lmask[b * Mm + t];
    __syncthreads();
    if (t == 0) {
        for (int rep = 0; rep < TOPN; rep++) {
            float bv = v[0]; int bi = 0;
            for (int m = 1; m < Mm; m++) { float x = v[m]; if (x > bv) { bv = x; bi = m; } }
            bidx[rep] = bi; v[bi] = -3.4e38f;
        }
    }
    __syncthreads();
    if (t < TOPN) out_idx[b * TOPN + t] = bidx[t];

    for (int tt = 0; tt < TOPN; tt++) {
        int m = bidx[tt];
        const float4* src = (const float4*)(land + ((size_t)(b * Mm + m)) * Dd);
        float4* dst = (float4*)(out_rows + ((size_t)(b * TOPN + tt)) * Dd);
        float part = 0.f;
        for (int j = t; j < D4; j += 128) {
            float4 x = src[j];
            dst[j] = x;
            part += dot4(x, x);
        }
        red[t] = part; __syncthreads();
        for (int off = 64; off > 0; off >>= 1) { if (t < off) red[t] += red[t + off]; __syncthreads(); }
        if (t == 0) out_norm[b * TOPN + tt] = sqrtf(red[0]);
        __syncthreads();
    }

    if (mode == 1) {
        if (t < TOPN * 6) {
            int tt = t / 6, r = t % 6;
            out_lrel[(b * TOPN + tt) * 6 + r] = lrel_src[((size_t)(b * Mm + bidx[tt])) * 6 + r];
        }
        if (t < TOPN) out_rmask[b * TOPN + t] = rmask_src[b * Mm + bidx[t]];
    }
}

// ---------------- K_pano ----------------
__global__ void k_pano(const float* __restrict__ pano_obj, const float* __restrict__ land_sel,
                       const float* __restrict__ land_norm, float* __restrict__ pano_sim)
{
    int b = blockIdx.y, p = blockIdx.x;
    int tid = threadIdx.x;              // 256
    int warp = tid >> 5, lane = tid & 31;
    __shared__ float4 land4[TOPN * D4];
    __shared__ float lnorm[TOPN];
    __shared__ float sim[OBJ][TOPN];
    __shared__ int best[TOPN];

    const float4* ls4 = (const float4*)(land_sel + (size_t)b * TOPN * Dd);
    for (int idx = tid; idx < TOPN * D4; idx += 256) land4[idx] = ls4[idx];
    if (tid < TOPN) lnorm[tid] = land_norm[b * TOPN + tid];
    __syncthreads();

    const float* obase = pano_obj + ((size_t)(b * PANO + p)) * OBJ * Dd;
    for (int o = warp; o < OBJ; o += 8) {
        const float4* row4 = (const float4*)(obase + (size_t)o * Dd);
        float a0 = 0, a1 = 0, a2 = 0, an = 0;
        for (int j = lane; j < D4; j += 32) {
            float4 f = row4[j];
            a0 += dot4(f, land4[j]);
            a1 += dot4(f, land4[D4 + j]);
            a2 += dot4(f, land4[2 * D4 + j]);
            an += dot4(f, f);
        }
        a0 = warp_sum(a0); a1 = warp_sum(a1); a2 = warp_sum(a2); an = warp_sum(an);
        if (lane == 0) {
            float no = sqrtf(an);
            sim[o][0] = a0 / fmaxf(no * lnorm[0], EPSV);
            sim[o][1] = a1 / fmaxf(no * lnorm[1], EPSV);
            sim[o][2] = a2 / fmaxf(no * lnorm[2], EPSV);
        }
    }
    __syncthreads();
    if (tid < TOPN) {
        float bv = sim[0][tid]; int bi = 0;
        for (int o = 1; o < OBJ; o++) { float s = sim[o][tid]; if (s > bv) { bv = s; bi = o; } }
        best[tid] = bi;
    }
    __syncthreads();
    float4* dst = (float4*)(pano_sim + ((size_t)(b * PANO + p)) * TOPN * Dd);
    for (int idx = tid; idx < TOPN * D4; idx += 256) {
        int tt = idx / D4, j = idx % D4;
        dst[idx] = ((const float4*)(obase + (size_t)best[tt] * Dd))[j];
    }
}

// ---------------- K_actemb ----------------
__global__ void k_actemb(const float* __restrict__ action, const float* __restrict__ embW,
                         const float* __restrict__ embb, float* __restrict__ x)
{
    int b = blockIdx.x, e = threadIdx.x;  // 64
    float acc = 0.f;
    #pragma unroll 4
    for (int a = 0; a < ANG; a++) acc += action[b * ANG + a] * embW[a * EMB + e];
    x[(size_t)b * XDIM + e] = tanhf(acc + embb[e]);
}

// ---------------- K_attn_a: fused partial combine + attention logits + softmax ----------------
__global__ void k_attn_a(const float* __restrict__ feature, const float* __restrict__ pano_sim,
                         const float* __restrict__ part, float* __restrict__ attn_p, int S)
{
    int b = blockIdx.x;
    int tid = threadIdx.x, warp = tid >> 5, lane = tid & 31; // 256
    __shared__ float4 qb4[F4A];
    __shared__ float aval[PANO];
    __shared__ float pvals[PANO];

    const float4* p4 = (const float4*)part;
    for (int j = tid; j < F4A; j += 256) {
        float4 s = make_float4(0.f, 0.f, 0.f, 0.f);
        for (int ss = 0; ss < S; ss++)
            s = f4add(s, p4[(size_t)(ss * Bz + b) * F4A + j]);
        qb4[j] = s;
    }
    __syncthreads();

    for (int s = warp; s < PANO; s += 8) {
        const float4* f4 = (const float4*)(feature + ((size_t)(b * PANO + s)) * FEAT);
        const float4* ps4 = (const float4*)(pano_sim + ((size_t)(b * PANO + s)) * TOPN * Dd);
        float acc = 0.f;
        for (int j = lane; j < F4F; j += 32) acc += dot4(f4[j], qb4[j]);
        for (int j = lane; j < F4P; j += 32) acc += dot4(ps4[j], qb4[F4F + j]);
        acc = warp_sum(acc);
        if (lane == 0) aval[s] = acc;
    }
    __syncthreads();
    if (tid == 0) {
        float mx = aval[0];
        for (int s = 1; s < PANO; s++) mx = fmaxf(mx, aval[s]);
        float sum = 0.f;
        for (int s = 0; s < PANO; s++) { float e = expf(aval[s] - mx); pvals[s] = e; sum += e; }
        float inv = 1.0f / sum;
        for (int s = 0; s < PANO; s++) pvals[s] *= inv;
    }
    __syncthreads();
    if (tid < PANO) attn_p[b * PANO + tid] = pvals[tid];
}

// ---------------- K_attn_feat: x[b, 64 + 4j..] = sum_s p[s]*feat_all4[b,s,j] ----------------
__global__ void k_attn_feat(const float* __restrict__ feature, const float* __restrict__ pano_sim,
                            const float* __restrict__ attn_p, float* __restrict__ x)
{
    int b = blockIdx.y;
    int j = blockIdx.x * 128 + threadIdx.x;   // float4 index into FEAT_ALL
    __shared__ float p[PANO];
    // FIX (R3 bug): shared load + barrier must come BEFORE the bounds return,
    // otherwise the tail block's early-exited threads never fill p[].
    if (threadIdx.x < PANO) p[threadIdx.x] = attn_p[b * PANO + threadIdx.x];
    __syncthreads();
    if (j >= F4A) return;
    float4 acc = make_float4(0.f, 0.f, 0.f, 0.f);
    if (j < F4F) {
        const float4* f4 = (const float4*)(feature + (size_t)b * PANO * FEAT) + j;
        #pragma unroll 4
        for (int s = 0; s < PANO; s++) {
            float4 v = f4[(size_t)s * F4F];
            float w = p[s];
            acc.x += w * v.x; acc.y += w * v.y; acc.z += w * v.z; acc.w += w * v.w;
        }
    } else {
        const float4* f4 = (const float4*)(pano_sim + (size_t)b * PANO * TOPN * Dd) + (j - F4F);
        #pragma unroll 4
        for (int s = 0; s < PANO; s++) {
            float4 v = f4[(size_t)s * F4P];
            float w = p[s];
            acc.x += w * v.x; acc.y += w * v.y; acc.z += w * v.z; acc.w += w * v.w;
        }
    }
    ((float4*)(x + (size_t)b * XDIM + EMB))[j] = acc;
}

// ---------------- K_ctx: fused q2 combine + ctx attention + wctx + concat ----------------
__global__ void k_ctx(const float* __restrict__ ctx, const float* __restrict__ part,
                      const float* __restrict__ h1, float* __restrict__ ctx_attn,
                      float* __restrict__ cat, int S)
{
    int b = blockIdx.x;
    int tid = threadIdx.x, warp = tid >> 5, lane = tid & 31; // 512 threads
    __shared__ float4 q2s[128];
    __shared__ float lg[CFG];
    __shared__ float pr[CFG];

    if (tid < 128) {
        const float4* p4 = (const float4*)part;
        float4 s = make_float4(0.f, 0.f, 0.f, 0.f);
        for (int ss = 0; ss < S; ss++)
            s = f4add(s, p4[(size_t)(ss * Bz + b) * 128 + tid]);
        q2s[tid] = s;
    }
    __syncthreads();
    {
        int s = warp; // 16 warps, one ctx row each
        const float4* c4 = (const float4*)(ctx + ((size_t)(b * CFG + s)) * Hh);
        float acc = 0.f;
        for (int j = lane; j < 128; j += 32) acc += dot4(c4[j], q2s[j]);
        acc = warp_sum(acc);
        if (lane == 0) lg[s] = acc;
    }
    __syncthreads();
    if (tid == 0) {
        float mx = lg[0];
        for (int s = 1; s < CFG; s++) mx = fmaxf(mx, lg[s]);
        float sum = 0.f;
        for (int s = 0; s < CFG; s++) { float e = expf(lg[s] - mx); pr[s] = e; sum += e; }
        float inv = 1.0f / sum;
        for (int s = 0; s < CFG; s++) pr[s] *= inv;
    }
    __syncthreads();
    if (tid < CFG) ctx_attn[b * CFG + tid] = pr[tid];
    if (tid < 128) {
        const float4* c4 = (const float4*)(ctx + (size_t)b * CFG * Hh) + tid;
        float4 acc = make_float4(0.f, 0.f, 0.f, 0.f);
        #pragma unroll
        for (int s = 0; s < CFG; s++) {
            float4 v = c4[(size_t)s * 128];
            float w = pr[s];
            acc.x += w * v.x; acc.y += w * v.y; acc.z += w * v.z; acc.w += w * v.w;
        }
        ((float4*)(cat + (size_t)b * 2 * Hh))[tid] = acc;
        ((float4*)(cat + (size_t)b * 2 * Hh + Hh))[tid] = ((const float4*)(h1 + (size_t)b * Hh))[tid];
    }
}

// ---------------- K_logit ----------------
__global__ void k_logit(const float* __restrict__ cand_obj, const float* __restrict__ cland,
                        const float* __restrict__ cland_norm, const float* __restrict__ cand_feat,
                        const float* __restrict__ crel_in, const float* __restrict__ lrel,
                        const float* __restrict__ rmask, const float* __restrict__ q3,
                        float* __restrict__ logit)
{
    int b = blockIdx.y, i = blockIdx.x;
    int tid = threadIdx.x, warp = tid >> 5, lane = tid & 31; // 256
    __shared__ float4 land4[TOPN * D4];
    __shared__ float lnorm[TOPN];
    __shared__ float sim[OBJ][TOPN];
    __shared__ int best[TOPN];
    __shared__ float red[256];

    const float4* ls4 = (const float4*)(cland + (size_t)b * TOPN * Dd);
    for (int idx = tid; idx < TOPN * D4; idx += 256) land4[idx] = ls4[idx];
    if (tid < TOPN) lnorm[tid] = cland_norm[b * TOPN + tid];
    __syncthreads();

    const float* obase = cand_obj + ((size_t)(b * IMG + i)) * OBJ * Dd;
    for (int o = warp; o < OBJ; o += 8) {
        const float4* row4 = (const float4*)(obase + (size_t)o * Dd);
        float a0 = 0, a1 = 0, a2 = 0, an = 0;
        for (int j = lane; j < D4; j += 32) {
            float4 f = row4[j];
            a0 += dot4(f, land4[j]);
            a1 += dot4(f, land4[D4 + j]);
            a2 += dot4(f, land4[2 * D4 + j]);
            an += dot4(f, f);
        }
        a0 = warp_sum(a0); a1 = warp_sum(a1); a2 = warp_sum(a2); an = warp_sum(an);
        if (lane == 0) {
            float no = sqrtf(an);
            sim[o][0] = a0 / fmaxf(no * lnorm[0], EPSV);
            sim[o][1] = a1 / fmaxf(no * lnorm[1], EPSV);
            sim[o][2] = a2 / fmaxf(no * lnorm[2], EPSV);
        }
    }
    __syncthreads();
    if (tid < TOPN) {
        float bv = sim[0][tid]; int bi = 0;
        for (int o = 1; o < OBJ; o++) { float s = sim[o][tid]; if (s > bv) { bv = s; bi = o; } }
        best[tid] = bi;
    }
    __syncthreads();

    const float* q = q3 + (size_t)b * CAND_PAD;
    const float4* q4 = (const float4*)q;
    const float4* cf4 = (const float4*)(cand_feat + ((size_t)(b * IMG + i)) * FEAT);
    float part = 0.f;
    for (int j = tid; j < F4F; j += 256) part += dot4(cf4[j], q4[j]);
    for (int idx = tid; idx < TOPN * D4; idx += 256) {
        int tt = idx / D4, j = idx % D4;
        float4 f = ((const float4*)(obase + (size_t)best[tt] * Dd))[j];
        const float* qs = q + FEAT + tt * (Dd + 7) + j * 4;
        part += f.x * qs[0] + f.y * qs[1] + f.z * qs[2] + f.w * qs[3];
    }
    red[tid] = part; __syncthreads();
    for (int off = 128; off > 0; off >>= 1) { if (tid < off) red[tid] += red[tid + off]; __syncthreads(); }
    if (tid == 0) {
        float s = red[0];
        const float* cr = crel_in + ((size_t)(b * IMG + i)) * 6;
        for (int tt = 0; tt < TOPN; tt++) {
            const float* qs = q + FEAT + tt * (Dd + 7);
            float rm = rmask[b * TOPN + tt];
            float lor = 0.f;
            #pragma unroll
            for (int r = 0; r < 6; r++) {
                lor += cr[r] * lrel[(b * TOPN + tt) * 6 + r];
                s += cr[r] * rm * qs[Dd + r];
            }
            s += lor * qs[Dd + 6];
        }
        logit[b * IMG + i] = s;
    }
}

// ---------------- launch ----------------
extern "C" void kernel_launch(void* const* d_in, const int* in_sizes, int n_in,
                              void* d_out, int out_size)
{
    const float* action     = (const float*)d_in[0];
    const float* feature    = (const float*)d_in[1];
    const float* cand_feat  = (const float*)d_in[2];
    const float* prev_h1    = (const float*)d_in[3];
    const float* c_0        = (const float*)d_in[4];
    const float* ctx        = (const float*)d_in[5];
    const float* s_0        = (const float*)d_in[6];
    const float* land       = (const float*)d_in[7];
    const float* cand_obj   = (const float*)d_in[8];
    const float* lmask      = (const float*)d_in[9];
    const float* lrel_in    = (const float*)d_in[10];
    const float* rmask_in   = (const float*)d_in[11];
    const float* crel_in    = (const float*)d_in[12];
    const float* pano_obj   = (const float*)d_in[13];
    const float* embW       = (const float*)d_in[14];
    const float* embb       = (const float*)d_in[15];
    const float* W_ih       = (const float*)d_in[16];
    const float* W_hh       = (const float*)d_in[17];
    const float* b_lstm     = (const float*)d_in[18];
    const float* feat_in_W  = (const float*)d_in[19];
    const float* att_in_W   = (const float*)d_in[20];
    const float* att_out_W  = (const float*)d_in[21];
    const float* cand_in_W  = (const float*)d_in[22];

    float* out   = (float*)d_out;
    float* h1    = out;
    float* c1    = out + Bz * Hh;
    float* logit = out + 2 * Bz * Hh;
    float* ht    = out + 2 * Bz * Hh + Bz * IMG;
    float* ctxa  = ht + Bz * Hh;

    int   *p_top, *p_ctop;
    float *p_lsel, *p_lnorm, *p_cland, *p_clnorm, *p_lrel, *p_rmask, *p_psim;
    float *p_ap, *p_x, *p_cat, *p_qc, *p_part;
    cudaGetSymbolAddress((void**)&p_top,    g_top_idx);
    cudaGetSymbolAddress((void**)&p_ctop,   g_ctop);
    cudaGetSymbolAddress((void**)&p_lsel,   g_land_sel);
    cudaGetSymbolAddress((void**)&p_lnorm,  g_land_norm);
    cudaGetSymbolAddress((void**)&p_cland,  g_cland);
    cudaGetSymbolAddress((void**)&p_clnorm, g_cland_norm);
    cudaGetSymbolAddress((void**)&p_lrel,   g_lrel);
    cudaGetSymbolAddress((void**)&p_rmask,  g_rmask);
    cudaGetSymbolAddress((void**)&p_psim,   g_pano_sim);
    cudaGetSymbolAddress((void**)&p_ap,     g_attn_p);
    cudaGetSymbolAddress((void**)&p_x,      g_x);
    cudaGetSymbolAddress((void**)&p_cat,    g_cat);
    cudaGetSymbolAddress((void**)&p_qc,     g_q_cand);
    cudaGetSymbolAddress((void**)&p_part,   g_part);

    // 1. top-3 landmark selection from s_0
    k_select<<<Bz, 128>>>(s_0, lmask, land, p_top, p_lsel, p_lnorm,
                          nullptr, nullptr, nullptr, nullptr, 0);
    // 2. pano cosine argmax + gather
    k_pano<<<dim3(PANO, Bz), 256>>>(pano_obj, p_lsel, p_lnorm, p_psim);
    // 3. action embedding -> x[:, :64]
    k_actemb<<<Bz, EMB>>>(action, embW, embb, p_x);
    // 4. q_feat partials = prev_h1 @ feat_in_W  (K=512, N=3076, S=8)
    gemm64v<true><<<dim3(25, 8), 256>>>(prev_h1, feat_in_W, p_part, Hh, FEAT_ALL, FEAT_ALL, 64, 0);
    // 5. attn logits+softmax (fused partial combine)
    k_attn_a<<<Bz, 256>>>(feature, p_psim, p_part, p_ap, 8);
    // 6. attn_feat -> x[:, 64:]
    k_attn_feat<<<dim3((F4A + 127) / 128, Bz), 128>>>(feature, p_psim, p_ap, p_x);
    // 7. gates: x@W_ih (splits 0..9) + prev_h1@W_hh (splits 10..13), fused cell
    gemm64v<true><<<dim3(16, 10), 256>>>(p_x, W_ih, p_part, XDIM, G4, G4, 320, 0);
    gemm64v<true><<<dim3(16, 4), 256>>>(prev_h1, W_hh, p_part, Hh, G4, G4, 128, 10);
    k_combine_cell<<<(Bz * Hh / 4 + 255) / 256, 256>>>(p_part, b_lstm, c_0, h1, c1, 14);
    // 9. q2 partials = h1 @ att_in_W  (S=8)
    gemm64v<true><<<dim3(4, 8), 256>>>(h1, att_in_W, p_part, Hh, Hh, Hh, 64, 0);
    // 10. ctx attention (fused q2 combine)
    k_ctx<<<Bz, 512>>>(ctx, p_part, h1, ctxa, p_cat, 8);
    // 11. h_tilde = tanh([wctx,h1] @ att_out_W)  (S=8)
    gemm64v<true><<<dim3(4, 8), 256>>>(p_cat, att_out_W, p_part, 2 * Hh, Hh, Hh, 128, 0);
    k_combine<<<(Bz * Hh / 4 + 255) / 256, 256>>>(p_part, ht, Bz * Hh / 4, 8, Bz * Hh / 4, 1);
    // 12. top-3 from ctx_attn + relation gathers
    k_select<<<Bz, 128>>>(ctxa, lmask, land, p_ctop, p_cland, p_clnorm,
                          lrel_in, rmask_in, p_lrel, p_rmask, 1);
    // 13. q3 = h_tilde @ cand_in_W  (N=3097, padded partials Np=3104, S=8)
    gemm64v<false><<<dim3(25, 8), 256>>>(ht, cand_in_W, p_part, Hh, CAND_ALL, CAND_PAD, 64, 0);
    k_combine<<<(Bz * CAND_PAD / 4 + 255) / 256, 256>>>(p_part, p_qc, Bz * CAND_PAD / 4, 8, Bz * CAND_PAD / 4, 0);
    // 14. candidate argmax + logits
    k_logit<<<dim3(IMG, Bz), 256>>>(cand_obj, p_cland, p_clnorm, cand_feat,
                                    crel_in, p_lrel, p_rmask, p_qc, logit);
}

// round 5
// speedup vs baseline: 3.8390x; 1.0984x over previous
#include <cuda_runtime.h>
#include <math.h>

// ---------------- problem constants ----------------
#define Bz   64
#define PANO 36
#define OBJ  36
#define CFG  16
#define LM   8
#define IMG  32
#define Dd   300
#define Hh   512
#define EMB  64
#define ANG  128
#define FEAT 2176
#define TOPN 3
#define Mm   128
#define FEAT_ALL 3076     // FEAT + TOPN*D
#define XDIM 3140         // EMB + FEAT_ALL
#define G4   2048         // 4*H
#define CAND_ALL 3097     // FEAT + TOPN*7 + TOPN*D
#define CAND_PAD 3104     // padded to /4
#define EPSV 1e-8f

#define F4A  769          // FEAT_ALL/4
#define F4F  544          // FEAT/4
#define F4P  225          // TOPN*Dd/4
#define D4   75           // Dd/4

// ---------------- scratch ----------------
__device__ int   g_top_idx[Bz * TOPN];
__device__ int   g_ctop[Bz * TOPN];
__device__ float g_land_sel[Bz * TOPN * Dd];
__device__ float g_land_norm[Bz * TOPN];
__device__ float g_cland[Bz * TOPN * Dd];
__device__ float g_cland_norm[Bz * TOPN];
__device__ float g_lrel[Bz * TOPN * 6];
__device__ float g_rmask[Bz * TOPN];
__device__ float g_pano_sim[(size_t)Bz * PANO * TOPN * Dd];
__device__ float g_attn_p[Bz * PANO];
__device__ float g_x[Bz * XDIM];
__device__ float g_cat[Bz * 2 * Hh];
__device__ float g_q_cand[Bz * CAND_PAD];
__device__ float g_part[3670016];   // split-K partials (max: 28 x 64 x 2048)

// ---------------- helpers ----------------
__device__ __forceinline__ float warp_sum(float v) {
    #pragma unroll
    for (int off = 16; off > 0; off >>= 1) v += __shfl_xor_sync(0xffffffffu, v, off);
    return v;
}
__device__ __forceinline__ float sigmoidf(float x) { return 1.0f / (1.0f + expf(-x)); }
__device__ __forceinline__ float dot4(float4 a, float4 b) {
    return a.x * b.x + a.y * b.y + a.z * b.z + a.w * b.w;
}
__device__ __forceinline__ float4 f4add(float4 a, float4 b) {
    return make_float4(a.x + b.x, a.y + b.y, a.z + b.z, a.w + b.w);
}
// ---- packed f32x2 (sm_103a FFMA2) ----
__device__ __forceinline__ unsigned long long bcast2(float v) {
    unsigned long long r;
    asm("mov.b64 %0, {%1, %1};" : "=l"(r) : "f"(v));
    return r;
}
__device__ __forceinline__ void fma2(unsigned long long& acc, unsigned long long a, unsigned long long b) {
    asm("fma.rn.f32x2 %0, %1, %2, %0;" : "+l"(acc) : "l"(a), "l"(b));
}
__device__ __forceinline__ float2 u2f(unsigned long long u) {
    float2 f;
    asm("mov.b64 {%0, %1}, %2;" : "=f"(f.x), "=f"(f.y) : "l"(u));
    return f;
}

// ================= GEMM: part[s][b][j](padded Np) = A[b, kbeg:kend] @ W[kbeg:kend, j] =========
// A [64,K] row-major (K%4==0, rows 16B aligned). W [K,N] row-major.
// Block: 256 threads -> 64(B) x 128(N) tile. Micro: 4(B) x 8(N) via f32x2 FMA. Double-buffered.
template<bool VECW>
__global__ void gemm64v(const float* __restrict__ A, const float* __restrict__ W,
                        float* __restrict__ part, int K, int N, int Np, int Kc, int split_base)
{
    __shared__ float As[2][32][64];
    __shared__ float Ws[2][32][128];
    const int jtile = blockIdx.x * 128;
    const int kbeg = blockIdx.y * Kc;
    const int kend = min(kbeg + Kc, K);
    const int tid = threadIdx.x;
    const int tx = tid & 15, ty = tid >> 4;
    const int nk = (kend - kbeg + 31) >> 5;

    float4 stA[2];
    float4 stW4[4];
    float  stWs[16];

    const int arow0 = tid >> 3, akq = tid & 7;

    auto loadRegs = [&](int k0) {
        #pragma unroll
        for (int r = 0; r < 2; r++) {
            int row = arow0 + r * 32;
            int kg = k0 + akq * 4;
            float4 v = make_float4(0.f, 0.f, 0.f, 0.f);
            if (kg < kend) v = *(const float4*)(A + (size_t)row * K + kg);
            stA[r] = v;
        }
        if (VECW) {
            #pragma unroll
            for (int r = 0; r < 4; r++) {
                int idx = tid + r * 256;
                int kk = idx >> 5, jq = idx & 31;
                int kg = k0 + kk, jg = jtile + jq * 4;
                float4 v = make_float4(0.f, 0.f, 0.f, 0.f);
                if (kg < kend && jg < N) v = *(const float4*)(W + (size_t)kg * N + jg);
                stW4[r] = v;
            }
        } else {
            #pragma unroll
            for (int r = 0; r < 16; r++) {
                int idx = tid + r * 256;
                int kk = idx >> 7, jj = idx & 127;
                int kg = k0 + kk, jg = jtile + jj;
                stWs[r] = (kg < kend && jg < N) ? W[(size_t)kg * N + jg] : 0.f;
            }
        }
    };
    auto storeSmem = [&](int buf) {
        #pragma unroll
        for (int r = 0; r < 2; r++) {
            int row = arow0 + r * 32;
            As[buf][akq * 4 + 0][row] = stA[r].x;
            As[buf][akq * 4 + 1][row] = stA[r].y;
            As[buf][akq * 4 + 2][row] = stA[r].z;
            As[buf][akq * 4 + 3][row] = stA[r].w;
        }
        if (VECW) {
            #pragma unroll
            for (int r = 0; r < 4; r++) {
                int idx = tid + r * 256;
                int kk = idx >> 5, jq = idx & 31;
                *(float4*)&Ws[buf][kk][jq * 4] = stW4[r];
            }
        } else {
            #pragma unroll
            for (int r = 0; r < 16; r++) {
                int idx = tid + r * 256;
                int kk = idx >> 7, jj = idx & 127;
                Ws[buf][kk][jj] = stWs[r];
            }
        }
    };

    unsigned long long acc[4][4] = {};  // [b][n-pair], each holds 2 adjacent n in f32x2

    loadRegs(kbeg);
    storeSmem(0);
    __syncthreads();

    for (int t = 0; t < nk; t++) {
        int cur = t & 1;
        if (t + 1 < nk) loadRegs(kbeg + (t + 1) * 32);
        #pragma unroll
        for (int kk = 0; kk < 32; kk++) {
            float4 a  = *(const float4*)&As[cur][kk][ty * 4];
            float4 b0 = *(const float4*)&Ws[cur][kk][tx * 8];
            float4 b1 = *(const float4*)&Ws[cur][kk][tx * 8 + 4];
            unsigned long long bp0 = *(unsigned long long*)&b0.x;
            unsigned long long bp1 = *(unsigned long long*)&b0.z;
            unsigned long long bp2 = *(unsigned long long*)&b1.x;
            unsigned long long bp3 = *(unsigned long long*)&b1.z;
            unsigned long long a0 = bcast2(a.x), a1 = bcast2(a.y), a2 = bcast2(a.z), a3 = bcast2(a.w);
            fma2(acc[0][0], a0, bp0); fma2(acc[0][1], a0, bp1); fma2(acc[0][2], a0, bp2); fma2(acc[0][3], a0, bp3);
            fma2(acc[1][0], a1, bp0); fma2(acc[1][1], a1, bp1); fma2(acc[1][2], a1, bp2); fma2(acc[1][3], a1, bp3);
            fma2(acc[2][0], a2, bp0); fma2(acc[2][1], a2, bp1); fma2(acc[2][2], a2, bp2); fma2(acc[2][3], a2, bp3);
            fma2(acc[3][0], a3, bp0); fma2(acc[3][1], a3, bp1); fma2(acc[3][2], a3, bp2); fma2(acc[3][3], a3, bp3);
        }
        if (t + 1 < nk) storeSmem(cur ^ 1);
        __syncthreads();
    }

    float* p = part + (size_t)(split_base + blockIdx.y) * ((size_t)Bz * Np);
    int j0 = jtile + tx * 8;
    #pragma unroll
    for (int i = 0; i < 4; i++) {
        int b = ty * 4 + i;
        float2 p0 = u2f(acc[i][0]), p1 = u2f(acc[i][1]), p2 = u2f(acc[i][2]), p3 = u2f(acc[i][3]);
        if (j0 < N)
            *(float4*)(p + (size_t)b * Np + j0) = make_float4(p0.x, p0.y, p1.x, p1.y);
        if (j0 + 4 < N)
            *(float4*)(p + (size_t)b * Np + j0 + 4) = make_float4(p2.x, p2.y, p3.x, p3.y);
    }
}

// combine: out4[i] = act( sum_s part4[s][i] )
__global__ void k_combine(const float* __restrict__ part, float* __restrict__ out,
                          int count4, int S, int stride4, int act)
{
    int idx = blockIdx.x * 256 + threadIdx.x;
    if (idx >= count4) return;
    const float4* p4 = (const float4*)part;
    float4 s = make_float4(0.f, 0.f, 0.f, 0.f);
    for (int ss = 0; ss < S; ss++) s = f4add(s, p4[(size_t)ss * stride4 + idx]);
    if (act) { s.x = tanhf(s.x); s.y = tanhf(s.y); s.z = tanhf(s.z); s.w = tanhf(s.w); }
    ((float4*)out)[idx] = s;
}

// combine gates partials (S splits, N=2048) + bias + LSTM cell; vectorized
__global__ void k_combine_cell(const float* __restrict__ part, const float* __restrict__ bias,
                               const float* __restrict__ c0,
                               float* __restrict__ h1, float* __restrict__ c1, int S)
{
    int idx = blockIdx.x * 256 + threadIdx.x;   // over Bz*Hh/4 = 8192
    if (idx >= Bz * Hh / 4) return;
    int b = idx >> 7, hq = idx & 127;
    const float4* p4 = (const float4*)part;
    const float4* b4 = (const float4*)bias;
    float4 g0 = b4[hq], g1 = b4[128 + hq], g2 = b4[256 + hq], g3 = b4[384 + hq];
    for (int ss = 0; ss < S; ss++) {
        const float4* pb = p4 + (size_t)(ss * Bz + b) * 512;
        g0 = f4add(g0, pb[hq]);
        g1 = f4add(g1, pb[128 + hq]);
        g2 = f4add(g2, pb[256 + hq]);
        g3 = f4add(g3, pb[384 + hq]);
    }
    float4 c0v = ((const float4*)c0)[idx];
    float4 cc, hh;
    {
        float ig = sigmoidf(g0.x), fg = sigmoidf(g1.x), gg = tanhf(g2.x), og = sigmoidf(g3.x);
        cc.x = fg * c0v.x + ig * gg; hh.x = og * tanhf(cc.x);
    }
    {
        float ig = sigmoidf(g0.y), fg = sigmoidf(g1.y), gg = tanhf(g2.y), og = sigmoidf(g3.y);
        cc.y = fg * c0v.y + ig * gg; hh.y = og * tanhf(cc.y);
    }
    {
        float ig = sigmoidf(g0.z), fg = sigmoidf(g1.z), gg = tanhf(g2.z), og = sigmoidf(g3.z);
        cc.z = fg * c0v.z + ig * gg; hh.z = og * tanhf(cc.z);
    }
    {
        float ig = sigmoidf(g0.w), fg = sigmoidf(g1.w), gg = tanhf(g2.w), og = sigmoidf(g3.w);
        cc.w = fg * c0v.w + ig * gg; hh.w = og * tanhf(cc.w);
    }
    ((float4*)c1)[idx] = cc;
    ((float4*)h1)[idx] = hh;
}

// ---------------- K_select ----------------
__global__ void k_select(const float* __restrict__ weights, const float* __restrict__ lmask,
                         const float* __restrict__ land, int* __restrict__ out_idx,
                         float* __restrict__ out_rows, float* __restrict__ out_norm,
                         const float* __restrict__ lrel_src, const float* __restrict__ rmask_src,
                         float* __restrict__ out_lrel, float* __restrict__ out_rmask, int mode)
{
    int b = blockIdx.x;
    int t = threadIdx.x;  // 128
    __shared__ float v[Mm];
    __shared__ int bidx[TOPN];
    __shared__ float red[128];

    v[t] = weights[b * CFG + (t >> 3)] * lmask[b * Mm + t];
    __syncthreads();
    if (t == 0) {
        for (int rep = 0; rep < TOPN; rep++) {
            float bv = v[0]; int bi = 0;
            for (int m = 1; m < Mm; m++) { float x = v[m]; if (x > bv) { bv = x; bi = m; } }
            bidx[rep] = bi; v[bi] = -3.4e38f;
        }
    }
    __syncthreads();
    if (t < TOPN) out_idx[b * TOPN + t] = bidx[t];

    for (int tt = 0; tt < TOPN; tt++) {
        int m = bidx[tt];
        const float4* src = (const float4*)(land + ((size_t)(b * Mm + m)) * Dd);
        float4* dst = (float4*)(out_rows + ((size_t)(b * TOPN + tt)) * Dd);
        float part = 0.f;
        for (int j = t; j < D4; j += 128) {
            float4 x = src[j];
            dst[j] = x;
            part += dot4(x, x);
        }
        red[t] = part; __syncthreads();
        for (int off = 64; off > 0; off >>= 1) { if (t < off) red[t] += red[t + off]; __syncthreads(); }
        if (t == 0) out_norm[b * TOPN + tt] = sqrtf(red[0]);
        __syncthreads();
    }

    if (mode == 1) {
        if (t < TOPN * 6) {
            int tt = t / 6, r = t % 6;
            out_lrel[(b * TOPN + tt) * 6 + r] = lrel_src[((size_t)(b * Mm + bidx[tt])) * 6 + r];
        }
        if (t < TOPN) out_rmask[b * TOPN + t] = rmask_src[b * Mm + bidx[t]];
    }
}

// ---------------- K_pano ----------------
__global__ void k_pano(const float* __restrict__ pano_obj, const float* __restrict__ land_sel,
                       const float* __restrict__ land_norm, float* __restrict__ pano_sim)
{
    int b = blockIdx.y, p = blockIdx.x;
    int tid = threadIdx.x;              // 256
    int warp = tid >> 5, lane = tid & 31;
    __shared__ float4 land4[TOPN * D4];
    __shared__ float lnorm[TOPN];
    __shared__ float sim[OBJ][TOPN];
    __shared__ int best[TOPN];

    const float4* ls4 = (const float4*)(land_sel + (size_t)b * TOPN * Dd);
    for (int idx = tid; idx < TOPN * D4; idx += 256) land4[idx] = ls4[idx];
    if (tid < TOPN) lnorm[tid] = land_norm[b * TOPN + tid];
    __syncthreads();

    const float* obase = pano_obj + ((size_t)(b * PANO + p)) * OBJ * Dd;
    for (int o = warp; o < OBJ; o += 8) {
        const float4* row4 = (const float4*)(obase + (size_t)o * Dd);
        float a0 = 0, a1 = 0, a2 = 0, an = 0;
        for (int j = lane; j < D4; j += 32) {
            float4 f = row4[j];
            a0 += dot4(f, land4[j]);
            a1 += dot4(f, land4[D4 + j]);
            a2 += dot4(f, land4[2 * D4 + j]);
            an += dot4(f, f);
        }
        a0 = warp_sum(a0); a1 = warp_sum(a1); a2 = warp_sum(a2); an = warp_sum(an);
        if (lane == 0) {
            float no = sqrtf(an);
            sim[o][0] = a0 / fmaxf(no * lnorm[0], EPSV);
            sim[o][1] = a1 / fmaxf(no * lnorm[1], EPSV);
            sim[o][2] = a2 / fmaxf(no * lnorm[2], EPSV);
        }
    }
    __syncthreads();
    if (tid < TOPN) {
        float bv = sim[0][tid]; int bi = 0;
        for (int o = 1; o < OBJ; o++) { float s = sim[o][tid]; if (s > bv) { bv = s; bi = o; } }
        best[tid] = bi;
    }
    __syncthreads();
    float4* dst = (float4*)(pano_sim + ((size_t)(b * PANO + p)) * TOPN * Dd);
    for (int idx = tid; idx < TOPN * D4; idx += 256) {
        int tt = idx / D4, j = idx % D4;
        dst[idx] = ((const float4*)(obase + (size_t)best[tt] * Dd))[j];
    }
}

// ---------------- K_actemb ----------------
__global__ void k_actemb(const float* __restrict__ action, const float* __restrict__ embW,
                         const float* __restrict__ embb, float* __restrict__ x)
{
    int b = blockIdx.x, e = threadIdx.x;  // 64
    float acc = 0.f;
    #pragma unroll 4
    for (int a = 0; a < ANG; a++) acc += action[b * ANG + a] * embW[a * EMB + e];
    x[(size_t)b * XDIM + e] = tanhf(acc + embb[e]);
}

// ---------------- K_attn_a: fused partial combine + attention logits + softmax ----------------
__global__ void k_attn_a(const float* __restrict__ feature, const float* __restrict__ pano_sim,
                         const float* __restrict__ part, float* __restrict__ attn_p, int S)
{
    int b = blockIdx.x;
    int tid = threadIdx.x, warp = tid >> 5, lane = tid & 31; // 512 threads
    __shared__ float4 qb4[F4A];
    __shared__ float aval[PANO];
    __shared__ float pvals[PANO];

    const float4* p4 = (const float4*)part;
    for (int j = tid; j < F4A; j += 512) {
        float4 s = make_float4(0.f, 0.f, 0.f, 0.f);
        for (int ss = 0; ss < S; ss++)
            s = f4add(s, p4[(size_t)(ss * Bz + b) * F4A + j]);
        qb4[j] = s;
    }
    __syncthreads();

    for (int s = warp; s < PANO; s += 16) {
        const float4* f4 = (const float4*)(feature + ((size_t)(b * PANO + s)) * FEAT);
        const float4* ps4 = (const float4*)(pano_sim + ((size_t)(b * PANO + s)) * TOPN * Dd);
        float acc = 0.f;
        for (int j = lane; j < F4F; j += 32) acc += dot4(f4[j], qb4[j]);
        for (int j = lane; j < F4P; j += 32) acc += dot4(ps4[j], qb4[F4F + j]);
        acc = warp_sum(acc);
        if (lane == 0) aval[s] = acc;
    }
    __syncthreads();
    if (tid == 0) {
        float mx = aval[0];
        for (int s = 1; s < PANO; s++) mx = fmaxf(mx, aval[s]);
        float sum = 0.f;
        for (int s = 0; s < PANO; s++) { float e = expf(aval[s] - mx); pvals[s] = e; sum += e; }
        float inv = 1.0f / sum;
        for (int s = 0; s < PANO; s++) pvals[s] *= inv;
    }
    __syncthreads();
    if (tid < PANO) attn_p[b * PANO + tid] = pvals[tid];
}

// ---------------- K_attn_feat ----------------
__global__ void k_attn_feat(const float* __restrict__ feature, const float* __restrict__ pano_sim,
                            const float* __restrict__ attn_p, float* __restrict__ x)
{
    int b = blockIdx.y;
    int j = blockIdx.x * 128 + threadIdx.x;   // float4 index into FEAT_ALL
    __shared__ float p[PANO];
    if (threadIdx.x < PANO) p[threadIdx.x] = attn_p[b * PANO + threadIdx.x];
    __syncthreads();
    if (j >= F4A) return;
    float4 acc = make_float4(0.f, 0.f, 0.f, 0.f);
    if (j < F4F) {
        const float4* f4 = (const float4*)(feature + (size_t)b * PANO * FEAT) + j;
        #pragma unroll 4
        for (int s = 0; s < PANO; s++) {
            float4 v = f4[(size_t)s * F4F];
            float w = p[s];
            acc.x += w * v.x; acc.y += w * v.y; acc.z += w * v.z; acc.w += w * v.w;
        }
    } else {
        const float4* f4 = (const float4*)(pano_sim + (size_t)b * PANO * TOPN * Dd) + (j - F4F);
        #pragma unroll 4
        for (int s = 0; s < PANO; s++) {
            float4 v = f4[(size_t)s * F4P];
            float w = p[s];
            acc.x += w * v.x; acc.y += w * v.y; acc.z += w * v.z; acc.w += w * v.w;
        }
    }
    ((float4*)(x + (size_t)b * XDIM + EMB))[j] = acc;
}

// ---------------- K_ctx ----------------
__global__ void k_ctx(const float* __restrict__ ctx, const float* __restrict__ part,
                      const float* __restrict__ h1, float* __restrict__ ctx_attn,
                      float* __restrict__ cat, int S)
{
    int b = blockIdx.x;
    int tid = threadIdx.x, warp = tid >> 5, lane = tid & 31; // 512 threads
    __shared__ float4 q2s[128];
    __shared__ float lg[CFG];
    __shared__ float pr[CFG];

    if (tid < 128) {
        const float4* p4 = (const float4*)part;
        float4 s = make_float4(0.f, 0.f, 0.f, 0.f);
        for (int ss = 0; ss < S; ss++)
            s = f4add(s, p4[(size_t)(ss * Bz + b) * 128 + tid]);
        q2s[tid] = s;
    }
    __syncthreads();
    {
        int s = warp;
        const float4* c4 = (const float4*)(ctx + ((size_t)(b * CFG + s)) * Hh);
        float acc = 0.f;
        for (int j = lane; j < 128; j += 32) acc += dot4(c4[j], q2s[j]);
        acc = warp_sum(acc);
        if (lane == 0) lg[s] = acc;
    }
    __syncthreads();
    if (tid == 0) {
        float mx = lg[0];
        for (int s = 1; s < CFG; s++) mx = fmaxf(mx, lg[s]);
        float sum = 0.f;
        for (int s = 0; s < CFG; s++) { float e = expf(lg[s] - mx); pr[s] = e; sum += e; }
        float inv = 1.0f / sum;
        for (int s = 0; s < CFG; s++) pr[s] *= inv;
    }
    __syncthreads();
    if (tid < CFG) ctx_attn[b * CFG + tid] = pr[tid];
    if (tid < 128) {
        const float4* c4 = (const float4*)(ctx + (size_t)b * CFG * Hh) + tid;
        float4 acc = make_float4(0.f, 0.f, 0.f, 0.f);
        #pragma unroll
        for (int s = 0; s < CFG; s++) {
            float4 v = c4[(size_t)s * 128];
            float w = pr[s];
            acc.x += w * v.x; acc.y += w * v.y; acc.z += w * v.z; acc.w += w * v.w;
        }
        ((float4*)(cat + (size_t)b * 2 * Hh))[tid] = acc;
        ((float4*)(cat + (size_t)b * 2 * Hh + Hh))[tid] = ((const float4*)(h1 + (size_t)b * Hh))[tid];
    }
}

// ---------------- K_logit ----------------
__global__ void k_logit(const float* __restrict__ cand_obj, const float* __restrict__ cland,
                        const float* __restrict__ cland_norm, const float* __restrict__ cand_feat,
                        const float* __restrict__ crel_in, const float* __restrict__ lrel,
                        const float* __restrict__ rmask, const float* __restrict__ q3,
                        float* __restrict__ logit)
{
    int b = blockIdx.y, i = blockIdx.x;
    int tid = threadIdx.x, warp = tid >> 5, lane = tid & 31; // 256
    __shared__ float4 land4[TOPN * D4];
    __shared__ float lnorm[TOPN];
    __shared__ float sim[OBJ][TOPN];
    __shared__ int best[TOPN];
    __shared__ float red[256];

    const float4* ls4 = (const float4*)(cland + (size_t)b * TOPN * Dd);
    for (int idx = tid; idx < TOPN * D4; idx += 256) land4[idx] = ls4[idx];
    if (tid < TOPN) lnorm[tid] = cland_norm[b * TOPN + tid];
    __syncthreads();

    const float* obase = cand_obj + ((size_t)(b * IMG + i)) * OBJ * Dd;
    for (int o = warp; o < OBJ; o += 8) {
        const float4* row4 = (const float4*)(obase + (size_t)o * Dd);
        float a0 = 0, a1 = 0, a2 = 0, an = 0;
        for (int j = lane; j < D4; j += 32) {
            float4 f = row4[j];
            a0 += dot4(f, land4[j]);
            a1 += dot4(f, land4[D4 + j]);
            a2 += dot4(f, land4[2 * D4 + j]);
            an += dot4(f, f);
        }
        a0 = warp_sum(a0); a1 = warp_sum(a1); a2 = warp_sum(a2); an = warp_sum(an);
        if (lane == 0) {
            float no = sqrtf(an);
            sim[o][0] = a0 / fmaxf(no * lnorm[0], EPSV);
            sim[o][1] = a1 / fmaxf(no * lnorm[1], EPSV);
            sim[o][2] = a2 / fmaxf(no * lnorm[2], EPSV);
        }
    }
    __syncthreads();
    if (tid < TOPN) {
        float bv = sim[0][tid]; int bi = 0;
        for (int o = 1; o < OBJ; o++) { float s = sim[o][tid]; if (s > bv) { bv = s; bi = o; } }
        best[tid] = bi;
    }
    __syncthreads();

    const float* q = q3 + (size_t)b * CAND_PAD;
    const float4* q4 = (const float4*)q;
    const float4* cf4 = (const float4*)(cand_feat + ((size_t)(b * IMG + i)) * FEAT);
    float part = 0.f;
    for (int j = tid; j < F4F; j += 256) part += dot4(cf4[j], q4[j]);
    for (int idx = tid; idx < TOPN * D4; idx += 256) {
        int tt = idx / D4, j = idx % D4;
        float4 f = ((const float4*)(obase + (size_t)best[tt] * Dd))[j];
        const float* qs = q + FEAT + tt * (Dd + 7) + j * 4;
        part += f.x * qs[0] + f.y * qs[1] + f.z * qs[2] + f.w * qs[3];
    }
    red[tid] = part; __syncthreads();
    for (int off = 128; off > 0; off >>= 1) { if (tid < off) red[tid] += red[tid + off]; __syncthreads(); }
    if (tid == 0) {
        float s = red[0];
        const float* cr = crel_in + ((size_t)(b * IMG + i)) * 6;
        for (int tt = 0; tt < TOPN; tt++) {
            const float* qs = q + FEAT + tt * (Dd + 7);
            float rm = rmask[b * TOPN + tt];
            float lor = 0.f;
            #pragma unroll
            for (int r = 0; r < 6; r++) {
                lor += cr[r] * lrel[(b * TOPN + tt) * 6 + r];
                s += cr[r] * rm * qs[Dd + r];
            }
            s += lor * qs[Dd + 6];
        }
        logit[b * IMG + i] = s;
    }
}

// ---------------- launch ----------------
extern "C" void kernel_launch(void* const* d_in, const int* in_sizes, int n_in,
                              void* d_out, int out_size)
{
    const float* action     = (const float*)d_in[0];
    const float* feature    = (const float*)d_in[1];
    const float* cand_feat  = (const float*)d_in[2];
    const float* prev_h1    = (const float*)d_in[3];
    const float* c_0        = (const float*)d_in[4];
    const float* ctx        = (const float*)d_in[5];
    const float* s_0        = (const float*)d_in[6];
    const float* land       = (const float*)d_in[7];
    const float* cand_obj   = (const float*)d_in[8];
    const float* lmask      = (const float*)d_in[9];
    const float* lrel_in    = (const float*)d_in[10];
    const float* rmask_in   = (const float*)d_in[11];
    const float* crel_in    = (const float*)d_in[12];
    const float* pano_obj   = (const float*)d_in[13];
    const float* embW       = (const float*)d_in[14];
    const float* embb       = (const float*)d_in[15];
    const float* W_ih       = (const float*)d_in[16];
    const float* W_hh       = (const float*)d_in[17];
    const float* b_lstm     = (const float*)d_in[18];
    const float* feat_in_W  = (const float*)d_in[19];
    const float* att_in_W   = (const float*)d_in[20];
    const float* att_out_W  = (const float*)d_in[21];
    const float* cand_in_W  = (const float*)d_in[22];

    float* out   = (float*)d_out;
    float* h1    = out;
    float* c1    = out + Bz * Hh;
    float* logit = out + 2 * Bz * Hh;
    float* ht    = out + 2 * Bz * Hh + Bz * IMG;
    float* ctxa  = ht + Bz * Hh;

    int   *p_top, *p_ctop;
    float *p_lsel, *p_lnorm, *p_cland, *p_clnorm, *p_lrel, *p_rmask, *p_psim;
    float *p_ap, *p_x, *p_cat, *p_qc, *p_part;
    cudaGetSymbolAddress((void**)&p_top,    g_top_idx);
    cudaGetSymbolAddress((void**)&p_ctop,   g_ctop);
    cudaGetSymbolAddress((void**)&p_lsel,   g_land_sel);
    cudaGetSymbolAddress((void**)&p_lnorm,  g_land_norm);
    cudaGetSymbolAddress((void**)&p_cland,  g_cland);
    cudaGetSymbolAddress((void**)&p_clnorm, g_cland_norm);
    cudaGetSymbolAddress((void**)&p_lrel,   g_lrel);
    cudaGetSymbolAddress((void**)&p_rmask,  g_rmask);
    cudaGetSymbolAddress((void**)&p_psim,   g_pano_sim);
    cudaGetSymbolAddress((void**)&p_ap,     g_attn_p);
    cudaGetSymbolAddress((void**)&p_x,      g_x);
    cudaGetSymbolAddress((void**)&p_cat,    g_cat);
    cudaGetSymbolAddress((void**)&p_qc,     g_q_cand);
    cudaGetSymbolAddress((void**)&p_part,   g_part);

    // 1. top-3 landmark selection from s_0
    k_select<<<Bz, 128>>>(s_0, lmask, land, p_top, p_lsel, p_lnorm,
                          nullptr, nullptr, nullptr, nullptr, 0);
    // 2. pano cosine argmax + gather
    k_pano<<<dim3(PANO, Bz), 256>>>(pano_obj, p_lsel, p_lnorm, p_psim);
    // 3. action embedding -> x[:, :64]
    k_actemb<<<Bz, EMB>>>(action, embW, embb, p_x);
    // 4. q_feat partials = prev_h1 @ feat_in_W  (K=512, N=3076, S=16)
    gemm64v<true><<<dim3(25, 16), 256>>>(prev_h1, feat_in_W, p_part, Hh, FEAT_ALL, FEAT_ALL, 32, 0);
    // 5. attn logits+softmax (fused partial combine)
    k_attn_a<<<Bz, 512>>>(feature, p_psim, p_part, p_ap, 16);
    // 6. attn_feat -> x[:, 64:]
    k_attn_feat<<<dim3((F4A + 127) / 128, Bz), 128>>>(feature, p_psim, p_ap, p_x);
    // 7. gates: x@W_ih (splits 0..19) + prev_h1@W_hh (splits 20..27), fused cell
    gemm64v<true><<<dim3(16, 20), 256>>>(p_x, W_ih, p_part, XDIM, G4, G4, 160, 0);
    gemm64v<true><<<dim3(16, 8), 256>>>(prev_h1, W_hh, p_part, Hh, G4, G4, 64, 20);
    k_combine_cell<<<(Bz * Hh / 4 + 255) / 256, 256>>>(p_part, b_lstm, c_0, h1, c1, 28);
    // 9. q2 partials = h1 @ att_in_W  (S=16)
    gemm64v<true><<<dim3(4, 16), 256>>>(h1, att_in_W, p_part, Hh, Hh, Hh, 32, 0);
    // 10. ctx attention (fused q2 combine)
    k_ctx<<<Bz, 512>>>(ctx, p_part, h1, ctxa, p_cat, 16);
    // 11. h_tilde = tanh([wctx,h1] @ att_out_W)  (S=16)
    gemm64v<true><<<dim3(4, 16), 256>>>(p_cat, att_out_W, p_part, 2 * Hh, Hh, Hh, 64, 0);
    k_combine<<<(Bz * Hh / 4 + 255) / 256, 256>>>(p_part, ht, Bz * Hh / 4, 16, Bz * Hh / 4, 1);
    // 12. top-3 from ctx_attn + relation gathers
    k_select<<<Bz, 128>>>(ctxa, lmask, land, p_ctop, p_cland, p_clnorm,
                          lrel_in, rmask_in, p_lrel, p_rmask, 1);
    // 13. q3 = h_tilde @ cand_in_W  (N=3097, padded partials Np=3104, S=16)
    gemm64v<false><<<dim3(25, 16), 256>>>(ht, cand_in_W, p_part, Hh, CAND_ALL, CAND_PAD, 32, 0);
    k_combine<<<(Bz * CAND_PAD / 4 + 255) / 256, 256>>>(p_part, p_qc, Bz * CAND_PAD / 4, 16, Bz * CAND_PAD / 4, 0);
    // 14. candidate argmax + logits
    k_logit<<<dim3(IMG, Bz), 256>>>(cand_obj, p_cland, p_clnorm, cand_feat,
                                    crel_in, p_lrel, p_rmask, p_qc, logit);
}

// round 7
// speedup vs baseline: 4.3501x; 1.1331x over previous
#include <cuda_runtime.h>
#include <math.h>

// ---------------- problem constants ----------------
#define Bz   64
#define PANO 36
#define OBJ  36
#define CFG  16
#define LM   8
#define IMG  32
#define Dd   300
#define Hh   512
#define EMB  64
#define ANG  128
#define FEAT 2176
#define TOPN 3
#define Mm   128
#define FEAT_ALL 3076     // FEAT + TOPN*D
#define XDIM 3140         // EMB + FEAT_ALL
#define G4   2048         // 4*H
#define CAND_ALL 3097     // FEAT + TOPN*7 + TOPN*D
#define CAND_PAD 3104     // padded to /4
#define EPSV 1e-8f

#define F4A  769          // FEAT_ALL/4
#define F4F  544          // FEAT/4
#define F4P  225          // TOPN*Dd/4
#define D4   75           // Dd/4

// ---------------- scratch ----------------
__device__ int   g_top_idx[Bz * TOPN];
__device__ int   g_ctop[Bz * TOPN];
__device__ float g_land_sel[Bz * TOPN * Dd];
__device__ float g_land_norm[Bz * TOPN];
__device__ float g_cland[Bz * TOPN * Dd];
__device__ float g_cland_norm[Bz * TOPN];
__device__ float g_lrel[Bz * TOPN * 6];
__device__ float g_rmask[Bz * TOPN];
__device__ float g_pano_sim[(size_t)Bz * PANO * TOPN * Dd];
__device__ float g_attn_p[Bz * PANO];
__device__ float g_x[Bz * XDIM];
__device__ float g_cat[Bz * 2 * Hh];
__device__ float g_q_cand[Bz * CAND_PAD];
__device__ float g_part[3670016];   // split-K partials (max: 28 x 64 x 2048)

// ---------------- helpers ----------------
__device__ __forceinline__ float warp_sum(float v) {
    #pragma unroll
    for (int off = 16; off > 0; off >>= 1) v += __shfl_xor_sync(0xffffffffu, v, off);
    return v;
}
__device__ __forceinline__ float sigmoidf(float x) { return 1.0f / (1.0f + expf(-x)); }
__device__ __forceinline__ float dot4(float4 a, float4 b) {
    return a.x * b.x + a.y * b.y + a.z * b.z + a.w * b.w;
}
__device__ __forceinline__ float4 f4add(float4 a, float4 b) {
    return make_float4(a.x + b.x, a.y + b.y, a.z + b.z, a.w + b.w);
}
// ---- packed f32x2 (sm_103a FFMA2) ----
__device__ __forceinline__ unsigned long long bcast2(float v) {
    unsigned long long r;
    asm("mov.b64 %0, {%1, %1};" : "=l"(r) : "f"(v));
    return r;
}
__device__ __forceinline__ void fma2(unsigned long long& acc, unsigned long long a, unsigned long long b) {
    asm("fma.rn.f32x2 %0, %1, %2, %0;" : "+l"(acc) : "l"(a), "l"(b));
}
__device__ __forceinline__ float2 u2f(unsigned long long u) {
    float2 f;
    asm("mov.b64 {%0, %1}, %2;" : "=f"(f.x), "=f"(f.y) : "l"(u));
    return f;
}

// ================= GEMM: part[s][b][j](stride Np) = A[b, kbeg:kend] @ W[kbeg:kend, j] =========
// A [64,K] row-major (K%4==0). W [K,N] row-major.
// Block: 128 threads -> 64(B) x 128(N) tile. Micro: 8(B) x 8(N) via f32x2. Double-buffered.
// Nck = ceil4(N): float4-store cap (requires Nck <= Np).
// VECW: float4 W loads (requires N%4==0). false -> scalar W loads (odd N).
#define ASTRIDE 72
template<bool VECW>
__global__ void __launch_bounds__(128)
gemm64w(const float* __restrict__ A, const float* __restrict__ W,
        float* __restrict__ part, int K, int N, int Nck, int Np, int Kc, int split_base)
{
    __shared__ float As[2][32][ASTRIDE];
    __shared__ float Ws[2][32][128];
    const int jtile = blockIdx.x * 128;
    const int kbeg = blockIdx.y * Kc;
    const int kend = min(kbeg + Kc, K);
    const int tid = threadIdx.x;
    const int tx = tid & 15, ty = tid >> 4;
    const int nk = (kend - kbeg + 31) >> 5;

    float4 stA[4];
    float4 stW[8];
    const int arow = tid >> 3, akq = tid & 7;   // A-load: 4 per thread (rows arow, arow+16, ...)

    auto loadRegs = [&](int k0) {
        #pragma unroll
        for (int r = 0; r < 4; r++) {
            int row = arow + r * 16;
            int kg = k0 + akq * 4;
            float4 v = make_float4(0.f, 0.f, 0.f, 0.f);
            if (kg < kend) v = *(const float4*)(A + (size_t)row * K + kg);
            stA[r] = v;
        }
        #pragma unroll
        for (int r = 0; r < 8; r++) {
            int idx = tid + r * 128;
            int kk = idx >> 5, jq = idx & 31;
            int kg = k0 + kk, jg = jtile + jq * 4;
            float4 v = make_float4(0.f, 0.f, 0.f, 0.f);
            if (kg < kend) {
                if (VECW) {
                    if (jg < N) v = *(const float4*)(W + (size_t)kg * N + jg);
                } else {
                    const float* wr = W + (size_t)kg * N;
                    if (jg < N)     v.x = wr[jg];
                    if (jg + 1 < N) v.y = wr[jg + 1];
                    if (jg + 2 < N) v.z = wr[jg + 2];
                    if (jg + 3 < N) v.w = wr[jg + 3];
                }
            }
            stW[r] = v;
        }
    };
    auto storeSmem = [&](int buf) {
        #pragma unroll
        for (int r = 0; r < 4; r++) {
            int row = arow + r * 16;
            As[buf][akq * 4 + 0][row] = stA[r].x;
            As[buf][akq * 4 + 1][row] = stA[r].y;
            As[buf][akq * 4 + 2][row] = stA[r].z;
            As[buf][akq * 4 + 3][row] = stA[r].w;
        }
        #pragma unroll
        for (int r = 0; r < 8; r++) {
            int idx = tid + r * 128;
            int kk = idx >> 5, jq = idx & 31;
            *(float4*)&Ws[buf][kk][jq * 4] = stW[r];
        }
    };

    unsigned long long acc[8][4] = {};   // [b-row][n-pair]

    loadRegs(kbeg);
    storeSmem(0);
    __syncthreads();

    for (int t = 0; t < nk; t++) {
        int cur = t & 1;
        if (t + 1 < nk) loadRegs(kbeg + (t + 1) * 32);
        #pragma unroll 8
        for (int kk = 0; kk < 32; kk++) {
            float4 aA = *(const float4*)&As[cur][kk][ty * 8];
            float4 aB = *(const float4*)&As[cur][kk][ty * 8 + 4];
            float4 b0 = *(const float4*)&Ws[cur][kk][tx * 8];
            float4 b1 = *(const float4*)&Ws[cur][kk][tx * 8 + 4];
            unsigned long long bp0 = *(unsigned long long*)&b0.x;
            unsigned long long bp1 = *(unsigned long long*)&b0.z;
            unsigned long long bp2 = *(unsigned long long*)&b1.x;
            unsigned long long bp3 = *(unsigned long long*)&b1.z;
            unsigned long long av;
            av = bcast2(aA.x); fma2(acc[0][0], av, bp0); fma2(acc[0][1], av, bp1); fma2(acc[0][2], av, bp2); fma2(acc[0][3], av, bp3);
            av = bcast2(aA.y); fma2(acc[1][0], av, bp0); fma2(acc[1][1], av, bp1); fma2(acc[1][2], av, bp2); fma2(acc[1][3], av, bp3);
            av = bcast2(aA.z); fma2(acc[2][0], av, bp0); fma2(acc[2][1], av, bp1); fma2(acc[2][2], av, bp2); fma2(acc[2][3], av, bp3);
            av = bcast2(aA.w); fma2(acc[3][0], av, bp0); fma2(acc[3][1], av, bp1); fma2(acc[3][2], av, bp2); fma2(acc[3][3], av, bp3);
            av = bcast2(aB.x); fma2(acc[4][0], av, bp0); fma2(acc[4][1], av, bp1); fma2(acc[4][2], av, bp2); fma2(acc[4][3], av, bp3);
            av = bcast2(aB.y); fma2(acc[5][0], av, bp0); fma2(acc[5][1], av, bp1); fma2(acc[5][2], av, bp2); fma2(acc[5][3], av, bp3);
            av = bcast2(aB.z); fma2(acc[6][0], av, bp0); fma2(acc[6][1], av, bp1); fma2(acc[6][2], av, bp2); fma2(acc[6][3], av, bp3);
            av = bcast2(aB.w); fma2(acc[7][0], av, bp0); fma2(acc[7][1], av, bp1); fma2(acc[7][2], av, bp2); fma2(acc[7][3], av, bp3);
        }
        if (t + 1 < nk) storeSmem(cur ^ 1);
        __syncthreads();
    }

    float* p = part + (size_t)(split_base + blockIdx.y) * ((size_t)Bz * Np);
    int j0 = jtile + tx * 8;
    #pragma unroll
    for (int i = 0; i < 8; i++) {
        int b = ty * 8 + i;
        float2 p0 = u2f(acc[i][0]), p1 = u2f(acc[i][1]), p2 = u2f(acc[i][2]), p3 = u2f(acc[i][3]);
        if (j0 + 4 <= Nck)
            *(float4*)(p + (size_t)b * Np + j0) = make_float4(p0.x, p0.y, p1.x, p1.y);
        if (j0 + 8 <= Nck)
            *(float4*)(p + (size_t)b * Np + j0 + 4) = make_float4(p2.x, p2.y, p3.x, p3.y);
    }
}

// combine: out4[i] = act( sum_s part4[s][i] )
__global__ void k_combine(const float* __restrict__ part, float* __restrict__ out,
                          int count4, int S, int stride4, int act)
{
    int idx = blockIdx.x * 256 + threadIdx.x;
    if (idx >= count4) return;
    const float4* p4 = (const float4*)part;
    float4 s = make_float4(0.f, 0.f, 0.f, 0.f);
    for (int ss = 0; ss < S; ss++) s = f4add(s, p4[(size_t)ss * stride4 + idx]);
    if (act) { s.x = tanhf(s.x); s.y = tanhf(s.y); s.z = tanhf(s.z); s.w = tanhf(s.w); }
    ((float4*)out)[idx] = s;
}

// combine gates partials (S splits, N=2048) + bias + LSTM cell; vectorized
__global__ void k_combine_cell(const float* __restrict__ part, const float* __restrict__ bias,
                               const float* __restrict__ c0,
                               float* __restrict__ h1, float* __restrict__ c1, int S)
{
    int idx = blockIdx.x * 256 + threadIdx.x;   // over Bz*Hh/4 = 8192
    if (idx >= Bz * Hh / 4) return;
    int b = idx >> 7, hq = idx & 127;
    const float4* p4 = (const float4*)part;
    const float4* b4 = (const float4*)bias;
    float4 g0 = b4[hq], g1 = b4[128 + hq], g2 = b4[256 + hq], g3 = b4[384 + hq];
    for (int ss = 0; ss < S; ss++) {
        const float4* pb = p4 + (size_t)(ss * Bz + b) * 512;
        g0 = f4add(g0, pb[hq]);
        g1 = f4add(g1, pb[128 + hq]);
        g2 = f4add(g2, pb[256 + hq]);
        g3 = f4add(g3, pb[384 + hq]);
    }
    float4 c0v = ((const float4*)c0)[idx];
    float4 cc, hh;
    {
        float ig = sigmoidf(g0.x), fg = sigmoidf(g1.x), gg = tanhf(g2.x), og = sigmoidf(g3.x);
        cc.x = fg * c0v.x + ig * gg; hh.x = og * tanhf(cc.x);
    }
    {
        float ig = sigmoidf(g0.y), fg = sigmoidf(g1.y), gg = tanhf(g2.y), og = sigmoidf(g3.y);
        cc.y = fg * c0v.y + ig * gg; hh.y = og * tanhf(cc.y);
    }
    {
        float ig = sigmoidf(g0.z), fg = sigmoidf(g1.z), gg = tanhf(g2.z), og = sigmoidf(g3.z);
        cc.z = fg * c0v.z + ig * gg; hh.z = og * tanhf(cc.z);
    }
    {
        float ig = sigmoidf(g0.w), fg = sigmoidf(g1.w), gg = tanhf(g2.w), og = sigmoidf(g3.w);
        cc.w = fg * c0v.w + ig * gg; hh.w = og * tanhf(cc.w);
    }
    ((float4*)c1)[idx] = cc;
    ((float4*)h1)[idx] = hh;
}

// ---------------- K_select ----------------
__global__ void k_select(const float* __restrict__ weights, const float* __restrict__ lmask,
                         const float* __restrict__ land, int* __restrict__ out_idx,
                         float* __restrict__ out_rows, float* __restrict__ out_norm,
                         const float* __restrict__ lrel_src, const float* __restrict__ rmask_src,
                         float* __restrict__ out_lrel, float* __restrict__ out_rmask, int mode)
{
    int b = blockIdx.x;
    int t = threadIdx.x;  // 128
    __shared__ float v[Mm];
    __shared__ int bidx[TOPN];
    __shared__ float red[128];

    v[t] = weights[b * CFG + (t >> 3)] * lmask[b * Mm + t];
    __syncthreads();
    if (t == 0) {
        for (int rep = 0; rep < TOPN; rep++) {
            float bv = v[0]; int bi = 0;
            for (int m = 1; m < Mm; m++) { float x = v[m]; if (x > bv) { bv = x; bi = m; } }
            bidx[rep] = bi; v[bi] = -3.4e38f;
        }
    }
    __syncthreads();
    if (t < TOPN) out_idx[b * TOPN + t] = bidx[t];

    for (int tt = 0; tt < TOPN; tt++) {
        int m = bidx[tt];
        const float4* src = (const float4*)(land + ((size_t)(b * Mm + m)) * Dd);
        float4* dst = (float4*)(out_rows + ((size_t)(b * TOPN + tt)) * Dd);
        float part = 0.f;
        for (int j = t; j < D4; j += 128) {
            float4 x = src[j];
            dst[j] = x;
            part += dot4(x, x);
        }
        red[t] = part; __syncthreads();
        for (int off = 64; off > 0; off >>= 1) { if (t < off) red[t] += red[t + off]; __syncthreads(); }
        if (t == 0) out_norm[b * TOPN + tt] = sqrtf(red[0]);
        __syncthreads();
    }

    if (mode == 1) {
        if (t < TOPN * 6) {
            int tt = t / 6, r = t % 6;
            out_lrel[(b * TOPN + tt) * 6 + r] = lrel_src[((size_t)(b * Mm + bidx[tt])) * 6 + r];
        }
        if (t < TOPN) out_rmask[b * TOPN + t] = rmask_src[b * Mm + bidx[t]];
    }
}

// ---------------- K_pano ----------------
__global__ void k_pano(const float* __restrict__ pano_obj, const float* __restrict__ land_sel,
                       const float* __restrict__ land_norm, float* __restrict__ pano_sim)
{
    int b = blockIdx.y, p = blockIdx.x;
    int tid = threadIdx.x;              // 256
    int warp = tid >> 5, lane = tid & 31;
    __shared__ float4 land4[TOPN * D4];
    __shared__ float lnorm[TOPN];
    __shared__ float sim[OBJ][TOPN];
    __shared__ int best[TOPN];

    const float4* ls4 = (const float4*)(land_sel + (size_t)b * TOPN * Dd);
    for (int idx = tid; idx < TOPN * D4; idx += 256) land4[idx] = ls4[idx];
    if (tid < TOPN) lnorm[tid] = land_norm[b * TOPN + tid];
    __syncthreads();

    const float* obase = pano_obj + ((size_t)(b * PANO + p)) * OBJ * Dd;
    for (int o = warp; o < OBJ; o += 8) {
        const float4* row4 = (const float4*)(obase + (size_t)o * Dd);
        float a0 = 0, a1 = 0, a2 = 0, an = 0;
        for (int j = lane; j < D4; j += 32) {
            float4 f = row4[j];
            a0 += dot4(f, land4[j]);
            a1 += dot4(f, land4[D4 + j]);
            a2 += dot4(f, land4[2 * D4 + j]);
            an += dot4(f, f);
        }
        a0 = warp_sum(a0); a1 = warp_sum(a1); a2 = warp_sum(a2); an = warp_sum(an);
        if (lane == 0) {
            float no = sqrtf(an);
            sim[o][0] = a0 / fmaxf(no * lnorm[0], EPSV);
            sim[o][1] = a1 / fmaxf(no * lnorm[1], EPSV);
            sim[o][2] = a2 / fmaxf(no * lnorm[2], EPSV);
        }
    }
    __syncthreads();
    if (tid < TOPN) {
        float bv = sim[0][tid]; int bi = 0;
        for (int o = 1; o < OBJ; o++) { float s = sim[o][tid]; if (s > bv) { bv = s; bi = o; } }
        best[tid] = bi;
    }
    __syncthreads();
    float4* dst = (float4*)(pano_sim + ((size_t)(b * PANO + p)) * TOPN * Dd);
    for (int idx = tid; idx < TOPN * D4; idx += 256) {
        int tt = idx / D4, j = idx % D4;
        dst[idx] = ((const float4*)(obase + (size_t)best[tt] * Dd))[j];
    }
}

// ---------------- K_actemb ----------------
__global__ void k_actemb(const float* __restrict__ action, const float* __restrict__ embW,
                         const float* __restrict__ embb, float* __restrict__ x)
{
    int b = blockIdx.x, e = threadIdx.x;  // 64
    float acc = 0.f;
    #pragma unroll 4
    for (int a = 0; a < ANG; a++) acc += action[b * ANG + a] * embW[a * EMB + e];
    x[(size_t)b * XDIM + e] = tanhf(acc + embb[e]);
}

// ---------------- K_attn_a: fused partial combine + attention logits + softmax ----------------
__global__ void k_attn_a(const float* __restrict__ feature, const float* __restrict__ pano_sim,
                         const float* __restrict__ part, float* __restrict__ attn_p, int S)
{
    int b = blockIdx.x;
    int tid = threadIdx.x, warp = tid >> 5, lane = tid & 31; // 512 threads
    __shared__ float4 qb4[F4A];
    __shared__ float aval[PANO];
    __shared__ float pvals[PANO];

    const float4* p4 = (const float4*)part;
    for (int j = tid; j < F4A; j += 512) {
        float4 s = make_float4(0.f, 0.f, 0.f, 0.f);
        for (int ss = 0; ss < S; ss++)
            s = f4add(s, p4[(size_t)(ss * Bz + b) * F4A + j]);
        qb4[j] = s;
    }
    __syncthreads();

    for (int s = warp; s < PANO; s += 16) {
        const float4* f4 = (const float4*)(feature + ((size_t)(b * PANO + s)) * FEAT);
        const float4* ps4 = (const float4*)(pano_sim + ((size_t)(b * PANO + s)) * TOPN * Dd);
        float acc = 0.f;
        for (int j = lane; j < F4F; j += 32) acc += dot4(f4[j], qb4[j]);
        for (int j = lane; j < F4P; j += 32) acc += dot4(ps4[j], qb4[F4F + j]);
        acc = warp_sum(acc);
        if (lane == 0) aval[s] = acc;
    }
    __syncthreads();
    if (tid == 0) {
        float mx = aval[0];
        for (int s = 1; s < PANO; s++) mx = fmaxf(mx, aval[s]);
        float sum = 0.f;
        for (int s = 0; s < PANO; s++) { float e = expf(aval[s] - mx); pvals[s] = e; sum += e; }
        float inv = 1.0f / sum;
        for (int s = 0; s < PANO; s++) pvals[s] *= inv;
    }
    __syncthreads();
    if (tid < PANO) attn_p[b * PANO + tid] = pvals[tid];
}

// ---------------- K_attn_feat ----------------
__global__ void k_attn_feat(const float* __restrict__ feature, const float* __restrict__ pano_sim,
                            const float* __restrict__ attn_p, float* __restrict__ x)
{
    int b = blockIdx.y;
    int j = blockIdx.x * 128 + threadIdx.x;   // float4 index into FEAT_ALL
    __shared__ float p[PANO];
    if (threadIdx.x < PANO) p[threadIdx.x] = attn_p[b * PANO + threadIdx.x];
    __syncthreads();
    if (j >= F4A) return;
    float4 acc = make_float4(0.f, 0.f, 0.f, 0.f);
    if (j < F4F) {
        const float4* f4 = (const float4*)(feature + (size_t)b * PANO * FEAT) + j;
        #pragma unroll 4
        for (int s = 0; s < PANO; s++) {
            float4 v = f4[(size_t)s * F4F];
            float w = p[s];
            acc.x += w * v.x; acc.y += w * v.y; acc.z += w * v.z; acc.w += w * v.w;
        }
    } else {
        const float4* f4 = (const float4*)(pano_sim + (size_t)b * PANO * TOPN * Dd) + (j - F4F);
        #pragma unroll 4
        for (int s = 0; s < PANO; s++) {
            float4 v = f4[(size_t)s * F4P];
            float w = p[s];
            acc.x += w * v.x; acc.y += w * v.y; acc.z += w * v.z; acc.w += w * v.w;
        }
    }
    ((float4*)(x + (size_t)b * XDIM + EMB))[j] = acc;
}

// ---------------- K_ctx ----------------
__global__ void k_ctx(const float* __restrict__ ctx, const float* __restrict__ part,
                      const float* __restrict__ h1, float* __restrict__ ctx_attn,
                      float* __restrict__ cat, int S)
{
    int b = blockIdx.x;
    int tid = threadIdx.x, warp = tid >> 5, lane = tid & 31; // 512 threads
    __shared__ float4 q2s[128];
    __shared__ float lg[CFG];
    __shared__ float pr[CFG];

    if (tid < 128) {
        const float4* p4 = (const float4*)part;
        float4 s = make_float4(0.f, 0.f, 0.f, 0.f);
        for (int ss = 0; ss < S; ss++)
            s = f4add(s, p4[(size_t)(ss * Bz + b) * 128 + tid]);
        q2s[tid] = s;
    }
    __syncthreads();
    {
        int s = warp;
        const float4* c4 = (const float4*)(ctx + ((size_t)(b * CFG + s)) * Hh);
        float acc = 0.f;
        for (int j = lane; j < 128; j += 32) acc += dot4(c4[j], q2s[j]);
        acc = warp_sum(acc);
        if (lane == 0) lg[s] = acc;
    }
    __syncthreads();
    if (tid == 0) {
        float mx = lg[0];
        for (int s = 1; s < CFG; s++) mx = fmaxf(mx, lg[s]);
        float sum = 0.f;
        for (int s = 0; s < CFG; s++) { float e = expf(lg[s] - mx); pr[s] = e; sum += e; }
        float inv = 1.0f / sum;
        for (int s = 0; s < CFG; s++) pr[s] *= inv;
    }
    __syncthreads();
    if (tid < CFG) ctx_attn[b * CFG + tid] = pr[tid];
    if (tid < 128) {
        const float4* c4 = (const float4*)(ctx + (size_t)b * CFG * Hh) + tid;
        float4 acc = make_float4(0.f, 0.f, 0.f, 0.f);
        #pragma unroll
        for (int s = 0; s < CFG; s++) {
            float4 v = c4[(size_t)s * 128];
            float w = pr[s];
            acc.x += w * v.x; acc.y += w * v.y; acc.z += w * v.z; acc.w += w * v.w;
        }
        ((float4*)(cat + (size_t)b * 2 * Hh))[tid] = acc;
        ((float4*)(cat + (size_t)b * 2 * Hh + Hh))[tid] = ((const float4*)(h1 + (size_t)b * Hh))[tid];
    }
}

// ---------------- K_logit ----------------
__global__ void k_logit(const float* __restrict__ cand_obj, const float* __restrict__ cland,
                        const float* __restrict__ cland_norm, const float* __restrict__ cand_feat,
                        const float* __restrict__ crel_in, const float* __restrict__ lrel,
                        const float* __restrict__ rmask, const float* __restrict__ q3,
                        float* __restrict__ logit)
{
    int b = blockIdx.y, i = blockIdx.x;
    int tid = threadIdx.x, warp = tid >> 5, lane = tid & 31; // 256
    __shared__ float4 land4[TOPN * D4];
    __shared__ float lnorm[TOPN];
    __shared__ float sim[OBJ][TOPN];
    __shared__ int best[TOPN];
    __shared__ float red[256];

    const float4* ls4 = (const float4*)(cland + (size_t)b * TOPN * Dd);
    for (int idx = tid; idx < TOPN * D4; idx += 256) land4[idx] = ls4[idx];
    if (tid < TOPN) lnorm[tid] = cland_norm[b * TOPN + tid];
    __syncthreads();

    const float* obase = cand_obj + ((size_t)(b * IMG + i)) * OBJ * Dd;
    for (int o = warp; o < OBJ; o += 8) {
        const float4* row4 = (const float4*)(obase + (size_t)o * Dd);
        float a0 = 0, a1 = 0, a2 = 0, an = 0;
        for (int j = lane; j < D4; j += 32) {
            float4 f = row4[j];
            a0 += dot4(f, land4[j]);
            a1 += dot4(f, land4[D4 + j]);
            a2 += dot4(f, land4[2 * D4 + j]);
            an += dot4(f, f);
        }
        a0 = warp_sum(a0); a1 = warp_sum(a1); a2 = warp_sum(a2); an = warp_sum(an);
        if (lane == 0) {
            float no = sqrtf(an);
            sim[o][0] = a0 / fmaxf(no * lnorm[0], EPSV);
            sim[o][1] = a1 / fmaxf(no * lnorm[1], EPSV);
            sim[o][2] = a2 / fmaxf(no * lnorm[2], EPSV);
        }
    }
    __syncthreads();
    if (tid < TOPN) {
        float bv = sim[0][tid]; int bi = 0;
        for (int o = 1; o < OBJ; o++) { float s = sim[o][tid]; if (s > bv) { bv = s; bi = o; } }
        best[tid] = bi;
    }
    __syncthreads();

    const float* q = q3 + (size_t)b * CAND_PAD;
    const float4* q4 = (const float4*)q;
    const float4* cf4 = (const float4*)(cand_feat + ((size_t)(b * IMG + i)) * FEAT);
    float part = 0.f;
    for (int j = tid; j < F4F; j += 256) part += dot4(cf4[j], q4[j]);
    for (int idx = tid; idx < TOPN * D4; idx += 256) {
        int tt = idx / D4, j = idx % D4;
        float4 f = ((const float4*)(obase + (size_t)best[tt] * Dd))[j];
        const float* qs = q + FEAT + tt * (Dd + 7) + j * 4;
        part += f.x * qs[0] + f.y * qs[1] + f.z * qs[2] + f.w * qs[3];
    }
    red[tid] = part; __syncthreads();
    for (int off = 128; off > 0; off >>= 1) { if (tid < off) red[tid] += red[tid + off]; __syncthreads(); }
    if (tid == 0) {
        float s = red[0];
        const float* cr = crel_in + ((size_t)(b * IMG + i)) * 6;
        for (int tt = 0; tt < TOPN; tt++) {
            const float* qs = q + FEAT + tt * (Dd + 7);
            float rm = rmask[b * TOPN + tt];
            float lor = 0.f;
            #pragma unroll
            for (int r = 0; r < 6; r++) {
                lor += cr[r] * lrel[(b * TOPN + tt) * 6 + r];
                s += cr[r] * rm * qs[Dd + r];
            }
            s += lor * qs[Dd + 6];
        }
        logit[b * IMG + i] = s;
    }
}

// ---------------- launch ----------------
extern "C" void kernel_launch(void* const* d_in, const int* in_sizes, int n_in,
                              void* d_out, int out_size)
{
    const float* action     = (const float*)d_in[0];
    const float* feature    = (const float*)d_in[1];
    const float* cand_feat  = (const float*)d_in[2];
    const float* prev_h1    = (const float*)d_in[3];
    const float* c_0        = (const float*)d_in[4];
    const float* ctx        = (const float*)d_in[5];
    const float* s_0        = (const float*)d_in[6];
    const float* land       = (const float*)d_in[7];
    const float* cand_obj   = (const float*)d_in[8];
    const float* lmask      = (const float*)d_in[9];
    const float* lrel_in    = (const float*)d_in[10];
    const float* rmask_in   = (const float*)d_in[11];
    const float* crel_in    = (const float*)d_in[12];
    const float* pano_obj   = (const float*)d_in[13];
    const float* embW       = (const float*)d_in[14];
    const float* embb       = (const float*)d_in[15];
    const float* W_ih       = (const float*)d_in[16];
    const float* W_hh       = (const float*)d_in[17];
    const float* b_lstm     = (const float*)d_in[18];
    const float* feat_in_W  = (const float*)d_in[19];
    const float* att_in_W   = (const float*)d_in[20];
    const float* att_out_W  = (const float*)d_in[21];
    const float* cand_in_W  = (const float*)d_in[22];

    float* out   = (float*)d_out;
    float* h1    = out;
    float* c1    = out + Bz * Hh;
    float* logit = out + 2 * Bz * Hh;
    float* ht    = out + 2 * Bz * Hh + Bz * IMG;
    float* ctxa  = ht + Bz * Hh;

    int   *p_top, *p_ctop;
    float *p_lsel, *p_lnorm, *p_cland, *p_clnorm, *p_lrel, *p_rmask, *p_psim;
    float *p_ap, *p_x, *p_cat, *p_qc, *p_part;
    cudaGetSymbolAddress((void**)&p_top,    g_top_idx);
    cudaGetSymbolAddress((void**)&p_ctop,   g_ctop);
    cudaGetSymbolAddress((void**)&p_lsel,   g_land_sel);
    cudaGetSymbolAddress((void**)&p_lnorm,  g_land_norm);
    cudaGetSymbolAddress((void**)&p_cland,  g_cland);
    cudaGetSymbolAddress((void**)&p_clnorm, g_cland_norm);
    cudaGetSymbolAddress((void**)&p_lrel,   g_lrel);
    cudaGetSymbolAddress((void**)&p_rmask,  g_rmask);
    cudaGetSymbolAddress((void**)&p_psim,   g_pano_sim);
    cudaGetSymbolAddress((void**)&p_ap,     g_attn_p);
    cudaGetSymbolAddress((void**)&p_x,      g_x);
    cudaGetSymbolAddress((void**)&p_cat,    g_cat);
    cudaGetSymbolAddress((void**)&p_qc,     g_q_cand);
    cudaGetSymbolAddress((void**)&p_part,   g_part);

    // 1. top-3 landmark selection from s_0
    k_select<<<Bz, 128>>>(s_0, lmask, land, p_top, p_lsel, p_lnorm,
                          nullptr, nullptr, nullptr, nullptr, 0);
    // 2. pano cosine argmax + gather
    k_pano<<<dim3(PANO, Bz), 256>>>(pano_obj, p_lsel, p_lnorm, p_psim);
    // 3. action embedding -> x[:, :64]
    k_actemb<<<Bz, EMB>>>(action, embW, embb, p_x);
    // 4. q_feat partials = prev_h1 @ feat_in_W  (K=512, S=8, Kc=64 -> nk=2)
    gemm64w<true><<<dim3(25, 8), 128>>>(prev_h1, feat_in_W, p_part, Hh, FEAT_ALL, FEAT_ALL, FEAT_ALL, 64, 0);
    // 5. attn logits+softmax (fused partial combine)
    k_attn_a<<<Bz, 512>>>(feature, p_psim, p_part, p_ap, 8);
    // 6. attn_feat -> x[:, 64:]
    k_attn_feat<<<dim3((F4A + 127) / 128, Bz), 128>>>(feature, p_psim, p_ap, p_x);
    // 7. gates: x@W_ih (splits 0..19, Kc=160 nk=5) + prev_h1@W_hh (splits 20..27, Kc=64 nk=2)
    gemm64w<true><<<dim3(16, 20), 128>>>(p_x, W_ih, p_part, XDIM, G4, G4, G4, 160, 0);
    gemm64w<true><<<dim3(16, 8), 128>>>(prev_h1, W_hh, p_part, Hh, G4, G4, G4, 64, 20);
    k_combine_cell<<<(Bz * Hh / 4 + 255) / 256, 256>>>(p_part, b_lstm, c_0, h1, c1, 28);
    // 9. q2 partials = h1 @ att_in_W  (S=16, Kc=32)
    gemm64w<true><<<dim3(4, 16), 128>>>(h1, att_in_W, p_part, Hh, Hh, Hh, Hh, 32, 0);
    // 10. ctx attention (fused q2 combine)
    k_ctx<<<Bz, 512>>>(ctx, p_part, h1, ctxa, p_cat, 16);
    // 11. h_tilde = tanh([wctx,h1] @ att_out_W)  (S=16, Kc=64 nk=2)
    gemm64w<true><<<dim3(4, 16), 128>>>(p_cat, att_out_W, p_part, 2 * Hh, Hh, Hh, Hh, 64, 0);
    k_combine<<<(Bz * Hh / 4 + 255) / 256, 256>>>(p_part, ht, Bz * Hh / 4, 16, Bz * Hh / 4, 1);
    // 12. top-3 from ctx_attn + relation gathers
    k_select<<<Bz, 128>>>(ctxa, lmask, land, p_ctop, p_cland, p_clnorm,
                          lrel_in, rmask_in, p_lrel, p_rmask, 1);
    // 13. q3 = h_tilde @ cand_in_W  (N=3097 odd -> scalar W loads; Nck=3100, Np=3104, S=8, Kc=64)
    gemm64w<false><<<dim3(25, 8), 128>>>(ht, cand_in_W, p_part, Hh, CAND_ALL, 3100, CAND_PAD, 64, 0);
    k_combine<<<(Bz * CAND_PAD / 4 + 255) / 256, 256>>>(p_part, p_qc, Bz * CAND_PAD / 4, 8, Bz * CAND_PAD / 4, 0);
    // 14. candidate argmax + logits
    k_logit<<<dim3(IMG, Bz), 256>>>(cand_obj, p_cland, p_clnorm, cand_feat,
                                    crel_in, p_lrel, p_rmask, p_qc, logit);
}